// round 11
// baseline (speedup 1.0000x reference)
#include <cuda_runtime.h>
#include <cuda_fp16.h>
#include <math.h>
#include <stdint.h>

#define EMB   1024
#define NH    16
#define HD    64
#define SEQ   2048
#define BATCH 2
#define MROWS (BATCH*SEQ)     // 4096
#define QKVN  (3*EMB)         // 3072
#define EPS   1.1920929e-07f

// ---- scratch (no allocations allowed) ----
__device__ float  g_qkv[(size_t)MROWS*QKVN];
__device__ __half g_nrm_h[(size_t)MROWS*EMB];
__device__ __half g_nrm_l[(size_t)MROWS*EMB];
__device__ __half g_att_h[(size_t)MROWS*EMB];
__device__ __half g_att_l[(size_t)MROWS*EMB];
__device__ __half g_wqkv_h[(size_t)QKVN*EMB];
__device__ __half g_wqkv_l[(size_t)QKVN*EMB];
__device__ __half g_wo_h[(size_t)EMB*EMB];
__device__ __half g_wo_l[(size_t)EMB*EMB];
__device__ __half g_qh[(size_t)BATCH*NH*SEQ*HD];
__device__ __half g_ql[(size_t)BATCH*NH*SEQ*HD];
__device__ __half g_kh[(size_t)BATCH*NH*SEQ*HD];
__device__ __half g_kl[(size_t)BATCH*NH*SEQ*HD];
__device__ __half g_vth[(size_t)BATCH*NH*HD*SEQ];
__device__ __half g_vtl[(size_t)BATCH*NH*HD*SEQ];

// ============================================================
// helpers
// ============================================================
__device__ __forceinline__ uint32_t smem_u32(const void* p) {
    uint32_t a;
    asm("{ .reg .u64 t; cvta.to.shared.u64 t, %1; cvt.u32.u64 %0, t; }" : "=r"(a) : "l"(p));
    return a;
}
__device__ __forceinline__ void split_f16(float x, __half& h, __half& l) {
    h = __float2half_rn(x);
    l = __float2half_rn(x - __half2float(h));
}
__device__ __forceinline__ void mma_f16(float* c, const uint32_t* a,
                                        uint32_t b0, uint32_t b1) {
    asm volatile(
        "mma.sync.aligned.m16n8k16.row.col.f32.f16.f16.f32 "
        "{%0,%1,%2,%3}, {%4,%5,%6,%7}, {%8,%9}, {%0,%1,%2,%3};"
        : "+f"(c[0]), "+f"(c[1]), "+f"(c[2]), "+f"(c[3])
        : "r"(a[0]), "r"(a[1]), "r"(a[2]), "r"(a[3]), "r"(b0), "r"(b1));
}
__device__ __forceinline__ void ldsm_x4(uint32_t* r, uint32_t addr) {
    asm volatile("ldmatrix.sync.aligned.m8n8.x4.shared.b16 {%0,%1,%2,%3}, [%4];"
        : "=r"(r[0]), "=r"(r[1]), "=r"(r[2]), "=r"(r[3]) : "r"(addr));
}
__device__ __forceinline__ void cp16(uint32_t sdst, const void* gsrc) {
    asm volatile("cp.async.cg.shared.global [%0], [%1], 16;" :: "r"(sdst), "l"(gsrc));
}
#define CP_COMMIT() asm volatile("cp.async.commit_group;")
#define CP_WAIT1()  asm volatile("cp.async.wait_group 1;")
#define CP_WAIT0()  asm volatile("cp.async.wait_group 0;")

// ============================================================
// weight fp16 hi/lo split
// ============================================================
__global__ __launch_bounds__(256) void conv_f16_kernel(
    const float* __restrict__ x, __half* __restrict__ hi, __half* __restrict__ lo)
{
    int i = blockIdx.x * 256 + threadIdx.x;
    float4 v = ((const float4*)x)[i];
    __half hx, lx, hy, ly, hz, lz, hw, lw;
    split_f16(v.x, hx, lx);  split_f16(v.y, hy, ly);
    split_f16(v.z, hz, lz);  split_f16(v.w, hw, lw);
    __half2 h01 = __halves2half2(hx, hy), h23 = __halves2half2(hz, hw);
    __half2 l01 = __halves2half2(lx, ly), l23 = __halves2half2(lz, lw);
    uint2 hp, lp;
    hp.x = *(uint32_t*)&h01; hp.y = *(uint32_t*)&h23;
    lp.x = *(uint32_t*)&l01; lp.y = *(uint32_t*)&l23;
    *(uint2*)(hi + (size_t)i*4) = hp;
    *(uint2*)(lo + (size_t)i*4) = lp;
}

// ============================================================
// GEMM via mma.sync fp16 (3x hi/lo), ldmatrix fragment loads
// CTA tile 128(M) x 64(N), K-chunk 64, double-buffered, 2 CTAs/SM
// ============================================================
#define STRW  36                      // words (u32) per smem row (72 halfs)
#define TWA   (128*STRW)
#define TWB   (64*STRW)
#define BUFW  (2*TWA + 2*TWB)
#define OFF_AH 0
#define OFF_AL TWA
#define OFF_BH (2*TWA)
#define OFF_BL (2*TWA + TWB)
#define GEMM_SMEM (2*BUFW*4)          // 110592 bytes

__global__ __launch_bounds__(256, 2) void gemm_f16_kernel(
    const __half* __restrict__ Ah, const __half* __restrict__ Al,
    const __half* __restrict__ Bh, const __half* __restrict__ Bl,
    const float* __restrict__ Res, float* __restrict__ C, int N)
{
    extern __shared__ __align__(16) uint32_t sg[];
    uint32_t sbase = smem_u32(sg);
    int tid = threadIdx.x;
    int m0 = blockIdx.y * 128, n0 = blockIdx.x * 64;
    int lane = tid & 31, wid = tid >> 5;
    int g = lane >> 2, t4 = lane & 3;
    int wm = wid & 3, wn = wid >> 2;
    int lg = lane >> 3, lr = lane & 7;

    // ldmatrix lane byte-offsets (within a tile)
    uint32_t aoff = (uint32_t)((wm*32 + (lg&1)*8 + lr)*STRW + (lg>>1)*4) * 4;
    uint32_t boff = (uint32_t)((wn*32 + (lg>>1)*8 + lr)*STRW + (lg&1)*4) * 4;

    float acc[2][4][4];
    #pragma unroll
    for (int mt = 0; mt < 2; mt++)
        #pragma unroll
        for (int nt = 0; nt < 4; nt++)
            #pragma unroll
            for (int r = 0; r < 4; r++) acc[mt][nt][r] = 0.0f;

    auto issue = [&](int ch) {
        int k0 = ch * 64;
        uint32_t bufw = (uint32_t)(ch & 1) * BUFW;
        #pragma unroll
        for (int i = 0; i < 12; i++) {
            int task = tid + i * 256;
            if (task < 2048) {
                int piece = task >> 10, rem = task & 1023;
                int row = rem >> 3, seg = rem & 7;
                const __half* src = (piece ? Al : Ah) + (size_t)(m0 + row)*1024 + k0 + seg*8;
                uint32_t sa = sbase + (bufw + (piece ? OFF_AL : OFF_AH) + row*STRW + seg*4)*4;
                cp16(sa, src);
            } else {
                int t2 = task - 2048;
                int piece = t2 >> 9, rem = t2 & 511;
                int row = rem >> 3, seg = rem & 7;
                const __half* src = (piece ? Bl : Bh) + (size_t)(n0 + row)*1024 + k0 + seg*8;
                uint32_t sa = sbase + (bufw + (piece ? OFF_BL : OFF_BH) + row*STRW + seg*4)*4;
                cp16(sa, src);
            }
        }
        CP_COMMIT();
    };

    issue(0);
    for (int ch = 0; ch < 16; ch++) {
        if (ch + 1 < 16) { issue(ch + 1); CP_WAIT1(); }
        else             { CP_WAIT0(); }
        __syncthreads();

        uint32_t bufb = ((uint32_t)(ch & 1) * BUFW) * 4;
        uint32_t baAH = sbase + bufb + OFF_AH*4 + aoff;
        uint32_t baAL = sbase + bufb + OFF_AL*4 + aoff;
        uint32_t baBH = sbase + bufb + OFF_BH*4 + boff;
        uint32_t baBL = sbase + bufb + OFF_BL*4 + boff;

        #pragma unroll
        for (int s = 0; s < 4; s++) {
            uint32_t sb = (uint32_t)s * 32;          // s*8 words
            uint32_t aH[2][4], aL[2][4];
            #pragma unroll
            for (int mt = 0; mt < 2; mt++) {
                ldsm_x4(aH[mt], baAH + (uint32_t)mt*(16*STRW*4) + sb);
                ldsm_x4(aL[mt], baAL + (uint32_t)mt*(16*STRW*4) + sb);
            }
            uint32_t bH[2][4], bL[2][4];
            #pragma unroll
            for (int p = 0; p < 2; p++) {
                ldsm_x4(bH[p], baBH + (uint32_t)p*(16*STRW*4) + sb);
                ldsm_x4(bL[p], baBL + (uint32_t)p*(16*STRW*4) + sb);
            }
            #pragma unroll
            for (int p = 0; p < 2; p++)
                #pragma unroll
                for (int q = 0; q < 2; q++) {
                    int nt = 2*p + q;
                    #pragma unroll
                    for (int mt = 0; mt < 2; mt++) {
                        mma_f16(acc[mt][nt], aH[mt], bH[p][2*q], bH[p][2*q+1]);
                        mma_f16(acc[mt][nt], aH[mt], bL[p][2*q], bL[p][2*q+1]);
                        mma_f16(acc[mt][nt], aL[mt], bH[p][2*q], bH[p][2*q+1]);
                    }
                }
        }
        __syncthreads();
    }

    #pragma unroll
    for (int mt = 0; mt < 2; mt++) {
        int r0 = m0 + wm*32 + mt*16 + g;
        int r1 = r0 + 8;
        #pragma unroll
        for (int nt = 0; nt < 4; nt++) {
            int col = n0 + wn*32 + nt*8 + t4*2;
            float2 v0 = make_float2(acc[mt][nt][0], acc[mt][nt][1]);
            float2 v1 = make_float2(acc[mt][nt][2], acc[mt][nt][3]);
            if (Res) {
                float2 q0 = *(const float2*)(Res + (size_t)r0*N + col);
                float2 q1 = *(const float2*)(Res + (size_t)r1*N + col);
                v0.x += q0.x; v0.y += q0.y;
                v1.x += q1.x; v1.y += q1.y;
            }
            *(float2*)(C + (size_t)r0*N + col) = v0;
            *(float2*)(C + (size_t)r1*N + col) = v1;
        }
    }
}

// ============================================================
// RMSNorm -> fp16 hi/lo
// ============================================================
__global__ __launch_bounds__(256) void rmsnorm_kernel(
    const float* __restrict__ x, const float* __restrict__ w,
    __half* __restrict__ out_h, __half* __restrict__ out_l)
{
    int row = blockIdx.x;
    int tid = threadIdx.x;
    const float4* xr = (const float4*)(x + (size_t)row*EMB);
    float4 v = xr[tid];
    float ss = v.x*v.x + v.y*v.y + v.z*v.z + v.w*v.w;
    #pragma unroll
    for (int o = 16; o > 0; o >>= 1) ss += __shfl_xor_sync(0xffffffffu, ss, o);
    __shared__ float wsum[8];
    if ((tid & 31) == 0) wsum[tid >> 5] = ss;
    __syncthreads();
    if (tid < 8) {
        float t = wsum[tid];
        #pragma unroll
        for (int o = 4; o > 0; o >>= 1) t += __shfl_xor_sync(0xffu, t, o);
        if (tid == 0) wsum[0] = t;
    }
    __syncthreads();
    float inv = rsqrtf(wsum[0] * (1.0f/EMB) + EPS);
    float4 wv = ((const float4*)w)[tid];
    float4 o4;
    o4.x = v.x*inv*wv.x; o4.y = v.y*inv*wv.y;
    o4.z = v.z*inv*wv.z; o4.w = v.w*inv*wv.w;
    __half hx, lx, hy, ly, hz, lz, hw, lw;
    split_f16(o4.x, hx, lx);  split_f16(o4.y, hy, ly);
    split_f16(o4.z, hz, lz);  split_f16(o4.w, hw, lw);
    __half2 h01 = __halves2half2(hx, hy), h23 = __halves2half2(hz, hw);
    __half2 l01 = __halves2half2(lx, ly), l23 = __halves2half2(lz, lw);
    uint2 hp, lp;
    hp.x = *(uint32_t*)&h01; hp.y = *(uint32_t*)&h23;
    lp.x = *(uint32_t*)&l01; lp.y = *(uint32_t*)&l23;
    *(uint2*)(out_h + (size_t)row*EMB + tid*4) = hp;
    *(uint2*)(out_l + (size_t)row*EMB + tid*4) = lp;
}

// ============================================================
// prep_qk: RoPE + (q: scale 1/8) + fp16 split -> [bh][s][64]
// ============================================================
__global__ __launch_bounds__(256) void prep_qk_kernel(
    const float* __restrict__ qkv, const float* __restrict__ cosb,
    const float* __restrict__ sinb,
    __half* __restrict__ qh, __half* __restrict__ ql,
    __half* __restrict__ kh, __half* __restrict__ kl)
{
    int idx = blockIdx.x * blockDim.x + threadIdx.x;   // 2^22
    int d  = idx & 31;
    int h  = (idx >> 5) & 15;
    int m  = (idx >> 9) & 4095;
    int t  = idx >> 21;                 // 0=q, 1=k
    int s  = m & (SEQ - 1);
    int b  = m >> 11;
    const float* p = qkv + (size_t)m*QKVN + t*EMB + h*HD;
    float x0 = p[d], x1 = p[d + 32];
    float c0 = cosb[s*HD + d],      c1 = cosb[s*HD + d + 32];
    float s0 = sinb[s*HD + d],      s1 = sinb[s*HD + d + 32];
    float r0 = c0*x0 + s0*x1;
    float r1 = c1*x1 + s1*x0;
    if (t == 0) { r0 *= 0.125f; r1 *= 0.125f; }
    __half* oh = (t ? kh : qh);
    __half* ol = (t ? kl : ql);
    size_t base = ((size_t)(b*NH + h)*SEQ + s)*HD;
    __half h0, l0, h1, l1;
    split_f16(r0, h0, l0);
    split_f16(r1, h1, l1);
    oh[base + d]      = h0;  ol[base + d]      = l0;
    oh[base + d + 32] = h1;  ol[base + d + 32] = l1;
}

// ============================================================
// prep_v: tiled transpose V -> [bh][d][s], fp16 hi/lo
// ============================================================
__global__ __launch_bounds__(256) void prep_v_kernel(
    const float* __restrict__ qkv, __half* __restrict__ vth, __half* __restrict__ vtl)
{
    __shared__ float ts[64*65];
    int st = blockIdx.x * 64, h = blockIdx.y, b = blockIdx.z;
    int tid = threadIdx.x;
    int row = tid >> 2, seg = tid & 3;
    const float* src = qkv + (size_t)(b*SEQ + st + row)*QKVN + 2*EMB + h*HD;
    #pragma unroll
    for (int j = 0; j < 4; j++) {
        int f4 = seg*4 + j;
        float4 v = *(const float4*)(src + f4*4);
        ts[row*65 + f4*4+0] = v.x; ts[row*65 + f4*4+1] = v.y;
        ts[row*65 + f4*4+2] = v.z; ts[row*65 + f4*4+3] = v.w;
    }
    __syncthreads();
    int d = tid >> 2, ss = tid & 3;
    __half hv[16], lv[16];
    #pragma unroll
    for (int j = 0; j < 16; j++) {
        float v = ts[(ss*16 + j)*65 + d];
        split_f16(v, hv[j], lv[j]);
    }
    size_t ob = ((size_t)((b*NH + h)*HD) + d)*SEQ + st + ss*16;
    #pragma unroll
    for (int j = 0; j < 4; j++) {
        __half2 a = __halves2half2(hv[4*j], hv[4*j+1]);
        __half2 c = __halves2half2(hv[4*j+2], hv[4*j+3]);
        uint2 pk; pk.x = *(uint32_t*)&a; pk.y = *(uint32_t*)&c;
        *(uint2*)(vth + ob + 4*j) = pk;
        __half2 a2 = __halves2half2(lv[4*j], lv[4*j+1]);
        __half2 c2 = __halves2half2(lv[4*j+2], lv[4*j+3]);
        uint2 pl; pl.x = *(uint32_t*)&a2; pl.y = *(uint32_t*)&c2;
        *(uint2*)(vtl + ob + 4*j) = pl;
    }
}

// ============================================================
// Tensor-core causal flash attention (ldmatrix fragment loads)
// ============================================================
#define QROWS 128
#define KSTRW 36
#define QSZW  (QROWS*KSTRW)
#define KSZW  (64*KSTRW)
#define F_QH 0
#define F_QL QSZW
#define F_KH (2*QSZW)
#define F_KL (2*QSZW + 2*KSZW)
#define F_VH (2*QSZW + 4*KSZW)
#define F_VL (2*QSZW + 6*KSZW)
#define FLASH_SMEM ((2*QSZW + 8*KSZW)*4)
#define PSTR (16*KSTRW*4)               // 16-row stride in bytes

__global__ __launch_bounds__(256, 1) void flash_mma_kernel(
    const __half* __restrict__ Qh, const __half* __restrict__ Ql,
    const __half* __restrict__ Kh, const __half* __restrict__ Kl,
    const __half* __restrict__ Vth, const __half* __restrict__ Vtl,
    __half* __restrict__ attn_h, __half* __restrict__ attn_l)
{
    extern __shared__ __align__(16) uint32_t sf[];
    uint32_t sbase = smem_u32(sf);
    int tid = threadIdx.x, lane = tid & 31, wid = tid >> 5;
    int g = lane >> 2, t4 = lane & 3;
    int lg = lane >> 3, lr = lane & 7;
    int qt = (gridDim.x - 1) - blockIdx.x;
    int h = blockIdx.y, b = blockIdx.z;
    int bh = b*NH + h;
    int q0 = qt * QROWS;
    int nkt = 2*(qt + 1);

    // ldmatrix lane byte-offsets
    uint32_t qoff = (uint32_t)((wid*16 + (lg&1)*8 + lr)*KSTRW + (lg>>1)*4) * 4;   // A-style
    uint32_t koff = (uint32_t)(((lg>>1)*8 + lr)*KSTRW + (lg&1)*4) * 4;            // B-style

    const __half* gQh = Qh  + (size_t)bh*SEQ*HD;
    const __half* gQl = Ql  + (size_t)bh*SEQ*HD;
    const __half* gKh = Kh  + (size_t)bh*SEQ*HD;
    const __half* gKl = Kl  + (size_t)bh*SEQ*HD;
    const __half* gVh = Vth + (size_t)bh*HD*SEQ;
    const __half* gVl = Vtl + (size_t)bh*HD*SEQ;

    auto issueKV = [&](int kt) {
        int k0 = kt * 64;
        uint32_t bufw = (uint32_t)(kt & 1) * KSZW;
        #pragma unroll
        for (int i = 0; i < 4; i++) {
            int task = tid + i*256;
            int piece = task >> 9, rem = task & 511;
            int row = rem >> 3, seg = rem & 7;
            const __half* src = (piece ? gKl : gKh) + (size_t)(k0 + row)*HD + seg*8;
            uint32_t dst = sbase + (((piece ? F_KL : F_KH) + bufw) + row*KSTRW + seg*4)*4;
            cp16(dst, src);
        }
        #pragma unroll
        for (int i = 0; i < 4; i++) {
            int task = tid + i*256;
            int piece = task >> 9, rem = task & 511;
            int row = rem >> 3, seg = rem & 7;
            const __half* src = (piece ? gVl : gVh) + (size_t)row*SEQ + k0 + seg*8;
            uint32_t dst = sbase + (((piece ? F_VL : F_VH) + bufw) + row*KSTRW + seg*4)*4;
            cp16(dst, src);
        }
    };

    #pragma unroll
    for (int i = 0; i < 8; i++) {
        int task = tid + i*256;
        int piece = task >> 10, rem = task & 1023;
        int row = rem >> 3, seg = rem & 7;
        const __half* src = (piece ? gQl : gQh) + (size_t)(q0 + row)*HD + seg*8;
        uint32_t dst = sbase + ((piece ? F_QL : F_QH) + row*KSTRW + seg*4)*4;
        cp16(dst, src);
    }
    issueKV(0);
    CP_COMMIT();

    float m0 = -INFINITY, m1 = -INFINITY, l0 = 0.f, l1 = 0.f;
    float o[8][4];
    #pragma unroll
    for (int dt = 0; dt < 8; dt++)
        #pragma unroll
        for (int e = 0; e < 4; e++) o[dt][e] = 0.f;

    uint32_t qbH = sbase + F_QH*4 + qoff;
    uint32_t qbL = sbase + F_QL*4 + qoff;

    for (int kt = 0; kt < nkt; kt++) {
        if (kt + 1 < nkt) { issueKV(kt + 1); CP_COMMIT(); CP_WAIT1(); }
        else              { CP_WAIT0(); }
        __syncthreads();

        uint32_t bufb = ((uint32_t)(kt & 1) * KSZW) * 4;
        uint32_t kbH = sbase + F_KH*4 + bufb + koff;
        uint32_t kbL = sbase + F_KL*4 + bufb + koff;
        uint32_t vbH = sbase + F_VH*4 + bufb + koff;
        uint32_t vbL = sbase + F_VL*4 + bufb + koff;

        // ---- scores: 3x fp16, ldmatrix ----
        float sc[8][4];
        #pragma unroll
        for (int nt = 0; nt < 8; nt++)
            #pragma unroll
            for (int e = 0; e < 4; e++) sc[nt][e] = 0.f;

        #pragma unroll
        for (int s = 0; s < 4; s++) {
            uint32_t sb = (uint32_t)s * 32;
            uint32_t aH[4], aL[4];
            ldsm_x4(aH, qbH + sb);
            ldsm_x4(aL, qbL + sb);
            #pragma unroll
            for (int p = 0; p < 4; p++) {
                uint32_t kH[4], kL[4];
                ldsm_x4(kH, kbH + (uint32_t)p*PSTR + sb);
                ldsm_x4(kL, kbL + (uint32_t)p*PSTR + sb);
                #pragma unroll
                for (int q = 0; q < 2; q++) {
                    int nt = 2*p + q;
                    mma_f16(sc[nt], aH, kH[2*q], kH[2*q+1]);
                    mma_f16(sc[nt], aH, kL[2*q], kL[2*q+1]);
                    mma_f16(sc[nt], aL, kH[2*q], kH[2*q+1]);
                }
            }
        }

        if (kt >= 2*qt) {
            int cb = kt*64;
            int r0 = q0 + wid*16 + g, r1 = r0 + 8;
            #pragma unroll
            for (int nt = 0; nt < 8; nt++) {
                int c0 = cb + nt*8 + 2*t4;
                if (c0     > r0) sc[nt][0] = -INFINITY;
                if (c0 + 1 > r0) sc[nt][1] = -INFINITY;
                if (c0     > r1) sc[nt][2] = -INFINITY;
                if (c0 + 1 > r1) sc[nt][3] = -INFINITY;
            }
        }

        float mt0 = -INFINITY, mt1 = -INFINITY;
        #pragma unroll
        for (int nt = 0; nt < 8; nt++) {
            mt0 = fmaxf(mt0, fmaxf(sc[nt][0], sc[nt][1]));
            mt1 = fmaxf(mt1, fmaxf(sc[nt][2], sc[nt][3]));
        }
        mt0 = fmaxf(mt0, __shfl_xor_sync(0xffffffffu, mt0, 1));
        mt0 = fmaxf(mt0, __shfl_xor_sync(0xffffffffu, mt0, 2));
        mt1 = fmaxf(mt1, __shfl_xor_sync(0xffffffffu, mt1, 1));
        mt1 = fmaxf(mt1, __shfl_xor_sync(0xffffffffu, mt1, 2));
        float mn0 = fmaxf(m0, mt0), mn1 = fmaxf(m1, mt1);
        float corr0 = __expf(m0 - mn0), corr1 = __expf(m1 - mn1);
        m0 = mn0; m1 = mn1;

        float ls0 = 0.f, ls1 = 0.f;
        uint32_t phA[8], phB[8], plA[8], plB[8];
        #pragma unroll
        for (int nt = 0; nt < 8; nt++) {
            float p0 = __expf(sc[nt][0] - mn0);
            float p1 = __expf(sc[nt][1] - mn0);
            float p2 = __expf(sc[nt][2] - mn1);
            float p3 = __expf(sc[nt][3] - mn1);
            ls0 += p0 + p1;  ls1 += p2 + p3;
            __half2 hA = __floats2half2_rn(p0, p1);
            float2 fA = __half22float2(hA);
            __half2 lA = __floats2half2_rn(p0 - fA.x, p1 - fA.y);
            __half2 hB = __floats2half2_rn(p2, p3);
            float2 fB = __half22float2(hB);
            __half2 lB = __floats2half2_rn(p2 - fB.x, p3 - fB.y);
            phA[nt] = *(uint32_t*)&hA;  plA[nt] = *(uint32_t*)&lA;
            phB[nt] = *(uint32_t*)&hB;  plB[nt] = *(uint32_t*)&lB;
        }
        ls0 += __shfl_xor_sync(0xffffffffu, ls0, 1);
        ls0 += __shfl_xor_sync(0xffffffffu, ls0, 2);
        ls1 += __shfl_xor_sync(0xffffffffu, ls1, 1);
        ls1 += __shfl_xor_sync(0xffffffffu, ls1, 2);
        l0 = l0*corr0 + ls0;
        l1 = l1*corr1 + ls1;
        #pragma unroll
        for (int dt = 0; dt < 8; dt++) {
            o[dt][0] *= corr0; o[dt][1] *= corr0;
            o[dt][2] *= corr1; o[dt][3] *= corr1;
        }

        // ---- PV: 3x fp16, ldmatrix ----
        #pragma unroll
        for (int kk = 0; kk < 4; kk++) {
            uint32_t aH[4] = { phA[2*kk], phB[2*kk], phA[2*kk+1], phB[2*kk+1] };
            uint32_t aL[4] = { plA[2*kk], plB[2*kk], plA[2*kk+1], plB[2*kk+1] };
            uint32_t kb = (uint32_t)kk * 32;
            #pragma unroll
            for (int p = 0; p < 4; p++) {
                uint32_t vH[4], vL[4];
                ldsm_x4(vH, vbH + (uint32_t)p*PSTR + kb);
                ldsm_x4(vL, vbL + (uint32_t)p*PSTR + kb);
                #pragma unroll
                for (int q = 0; q < 2; q++) {
                    int dt = 2*p + q;
                    mma_f16(o[dt], aH, vH[2*q], vH[2*q+1]);
                    mma_f16(o[dt], aH, vL[2*q], vL[2*q+1]);
                    mma_f16(o[dt], aL, vH[2*q], vH[2*q+1]);
                }
            }
        }
        __syncthreads();
    }

    float il0 = 1.0f / l0, il1 = 1.0f / l1;
    int r0g = b*SEQ + q0 + wid*16 + g;
    int r1g = r0g + 8;
    int cbase = h*HD;
    #pragma unroll
    for (int dt = 0; dt < 8; dt++) {
        int c = cbase + dt*8 + 2*t4;
        float v0 = o[dt][0]*il0, v1 = o[dt][1]*il0;
        float v2 = o[dt][2]*il1, v3 = o[dt][3]*il1;
        __half h0,l0h,h1,l1h,h2,l2h,h3,l3h;
        split_f16(v0, h0, l0h);  split_f16(v1, h1, l1h);
        split_f16(v2, h2, l2h);  split_f16(v3, h3, l3h);
        __half2 ha = __halves2half2(h0, h1), la = __halves2half2(l0h, l1h);
        __half2 hb = __halves2half2(h2, h3), lb = __halves2half2(l2h, l3h);
        *(uint32_t*)(attn_h + (size_t)r0g*EMB + c) = *(uint32_t*)&ha;
        *(uint32_t*)(attn_l + (size_t)r0g*EMB + c) = *(uint32_t*)&la;
        *(uint32_t*)(attn_h + (size_t)r1g*EMB + c) = *(uint32_t*)&hb;
        *(uint32_t*)(attn_l + (size_t)r1g*EMB + c) = *(uint32_t*)&lb;
    }
}

// ============================================================
// launch
// ============================================================
extern "C" void kernel_launch(void* const* d_in, const int* in_sizes, int n_in,
                              void* d_out, int out_size)
{
    const float* emb  = (const float*)d_in[0];
    const float* cosb = (const float*)d_in[1];
    const float* sinb = (const float*)d_in[2];
    const float* nw   = (const float*)d_in[3];
    const float* qkvw = (const float*)d_in[4];
    const float* ow   = (const float*)d_in[5];
    float* out = (float*)d_out;

    float* qkv;
    __half *nh, *nl, *ah, *al, *wqh, *wql, *woh, *wol;
    __half *qh, *ql, *kh, *kl, *vth, *vtl;
    cudaGetSymbolAddress((void**)&qkv, g_qkv);
    cudaGetSymbolAddress((void**)&nh,  g_nrm_h);
    cudaGetSymbolAddress((void**)&nl,  g_nrm_l);
    cudaGetSymbolAddress((void**)&ah,  g_att_h);
    cudaGetSymbolAddress((void**)&al,  g_att_l);
    cudaGetSymbolAddress((void**)&wqh, g_wqkv_h);
    cudaGetSymbolAddress((void**)&wql, g_wqkv_l);
    cudaGetSymbolAddress((void**)&woh, g_wo_h);
    cudaGetSymbolAddress((void**)&wol, g_wo_l);
    cudaGetSymbolAddress((void**)&qh,  g_qh);
    cudaGetSymbolAddress((void**)&ql,  g_ql);
    cudaGetSymbolAddress((void**)&kh,  g_kh);
    cudaGetSymbolAddress((void**)&kl,  g_kl);
    cudaGetSymbolAddress((void**)&vth, g_vth);
    cudaGetSymbolAddress((void**)&vtl, g_vtl);

    cudaFuncSetAttribute(gemm_f16_kernel,
        cudaFuncAttributeMaxDynamicSharedMemorySize, GEMM_SMEM);
    cudaFuncSetAttribute(flash_mma_kernel,
        cudaFuncAttributeMaxDynamicSharedMemorySize, FLASH_SMEM);

    conv_f16_kernel<<<(QKVN*EMB/4)/256, 256>>>(qkvw, wqh, wql);
    conv_f16_kernel<<<(EMB*EMB/4)/256, 256>>>(ow, woh, wol);
    rmsnorm_kernel<<<MROWS, 256>>>(emb, nw, nh, nl);
    gemm_f16_kernel<<<dim3(QKVN/64, MROWS/128), 256, GEMM_SMEM>>>(
        nh, nl, wqh, wql, nullptr, qkv, QKVN);
    prep_qk_kernel<<<(2*MROWS*NH*32)/256, 256>>>(qkv, cosb, sinb, qh, ql, kh, kl);
    prep_v_kernel<<<dim3(SEQ/64, NH, BATCH), 256>>>(qkv, vth, vtl);
    flash_mma_kernel<<<dim3(SEQ/QROWS, NH, BATCH), 256, FLASH_SMEM>>>(
        qh, ql, kh, kl, vth, vtl, ah, al);
    gemm_f16_kernel<<<dim3(EMB/64, MROWS/128), 256, GEMM_SMEM>>>(
        ah, al, woh, wol, emb, out, EMB);
}

// round 12
// speedup vs baseline: 1.6176x; 1.6176x over previous
#include <cuda_runtime.h>
#include <cuda_fp16.h>
#include <math.h>
#include <stdint.h>

#define EMB   1024
#define NH    16
#define HD    64
#define SEQ   2048
#define BATCH 2
#define MROWS (BATCH*SEQ)     // 4096
#define QKVN  (3*EMB)         // 3072
#define EPS   1.1920929e-07f

// ---- scratch (no allocations allowed) ----
__device__ float  g_qkv[(size_t)MROWS*QKVN];
__device__ __half g_nrm_h[(size_t)MROWS*EMB];
__device__ __half g_nrm_l[(size_t)MROWS*EMB];
__device__ __half g_att_h[(size_t)MROWS*EMB];
__device__ __half g_att_l[(size_t)MROWS*EMB];
__device__ __half g_wqkv_h[(size_t)QKVN*EMB];
__device__ __half g_wqkv_l[(size_t)QKVN*EMB];
__device__ __half g_wo_h[(size_t)EMB*EMB];
__device__ __half g_wo_l[(size_t)EMB*EMB];
__device__ __half g_qh[(size_t)BATCH*NH*SEQ*HD];
__device__ __half g_ql[(size_t)BATCH*NH*SEQ*HD];
__device__ __half g_kh[(size_t)BATCH*NH*SEQ*HD];
__device__ __half g_kl[(size_t)BATCH*NH*SEQ*HD];
__device__ __half g_vth[(size_t)BATCH*NH*HD*SEQ];

// ============================================================
// helpers
// ============================================================
__device__ __forceinline__ uint32_t smem_u32(const void* p) {
    uint32_t a;
    asm("{ .reg .u64 t; cvta.to.shared.u64 t, %1; cvt.u32.u64 %0, t; }" : "=r"(a) : "l"(p));
    return a;
}
__device__ __forceinline__ void split_f16(float x, __half& h, __half& l) {
    h = __float2half_rn(x);
    l = __float2half_rn(x - __half2float(h));
}
__device__ __forceinline__ void mma_f16(float* c, const uint32_t* a,
                                        uint32_t b0, uint32_t b1) {
    asm volatile(
        "mma.sync.aligned.m16n8k16.row.col.f32.f16.f16.f32 "
        "{%0,%1,%2,%3}, {%4,%5,%6,%7}, {%8,%9}, {%0,%1,%2,%3};"
        : "+f"(c[0]), "+f"(c[1]), "+f"(c[2]), "+f"(c[3])
        : "r"(a[0]), "r"(a[1]), "r"(a[2]), "r"(a[3]), "r"(b0), "r"(b1));
}
__device__ __forceinline__ void cp16(uint32_t sdst, const void* gsrc) {
    asm volatile("cp.async.cg.shared.global [%0], [%1], 16;" :: "r"(sdst), "l"(gsrc));
}
#define CP_COMMIT() asm volatile("cp.async.commit_group;")
#define CP_WAIT1()  asm volatile("cp.async.wait_group 1;")
#define CP_WAIT0()  asm volatile("cp.async.wait_group 0;")

// ============================================================
// weight fp16 hi/lo split
// ============================================================
__global__ __launch_bounds__(256) void conv_f16_kernel(
    const float* __restrict__ x, __half* __restrict__ hi, __half* __restrict__ lo)
{
    int i = blockIdx.x * 256 + threadIdx.x;
    float4 v = ((const float4*)x)[i];
    __half hx, lx, hy, ly, hz, lz, hw, lw;
    split_f16(v.x, hx, lx);  split_f16(v.y, hy, ly);
    split_f16(v.z, hz, lz);  split_f16(v.w, hw, lw);
    __half2 h01 = __halves2half2(hx, hy), h23 = __halves2half2(hz, hw);
    __half2 l01 = __halves2half2(lx, ly), l23 = __halves2half2(lz, lw);
    uint2 hp, lp;
    hp.x = *(uint32_t*)&h01; hp.y = *(uint32_t*)&h23;
    lp.x = *(uint32_t*)&l01; lp.y = *(uint32_t*)&l23;
    *(uint2*)(hi + (size_t)i*4) = hp;
    *(uint2*)(lo + (size_t)i*4) = lp;
}

// ============================================================
// GEMM via mma.sync fp16 (3x hi/lo) — round-9 config (best)
// CTA tile 128(M) x 64(N), K-chunk 64, double-buffered, 2 CTAs/SM
// ============================================================
#define STRW  36                      // words (u32) per smem row (72 halfs)
#define TWA   (128*STRW)
#define TWB   (64*STRW)
#define BUFW  (2*TWA + 2*TWB)
#define OFF_AH 0
#define OFF_AL TWA
#define OFF_BH (2*TWA)
#define OFF_BL (2*TWA + TWB)
#define GEMM_SMEM (2*BUFW*4)          // 110592 bytes

__global__ __launch_bounds__(256, 2) void gemm_f16_kernel(
    const __half* __restrict__ Ah, const __half* __restrict__ Al,
    const __half* __restrict__ Bh, const __half* __restrict__ Bl,
    const float* __restrict__ Res, float* __restrict__ C, int N)
{
    extern __shared__ __align__(16) uint32_t sg[];
    uint32_t sbase = smem_u32(sg);
    int tid = threadIdx.x;
    int m0 = blockIdx.y * 128, n0 = blockIdx.x * 64;
    int lane = tid & 31, wid = tid >> 5;
    int g = lane >> 2, t4 = lane & 3;
    int wm = wid & 3, wn = wid >> 2;

    float acc[2][4][4];
    #pragma unroll
    for (int mt = 0; mt < 2; mt++)
        #pragma unroll
        for (int nt = 0; nt < 4; nt++)
            #pragma unroll
            for (int r = 0; r < 4; r++) acc[mt][nt][r] = 0.0f;

    auto issue = [&](int ch) {
        int k0 = ch * 64;
        uint32_t bufw = (uint32_t)(ch & 1) * BUFW;
        #pragma unroll
        for (int i = 0; i < 12; i++) {
            int task = tid + i * 256;
            if (task < 2048) {
                int piece = task >> 10, rem = task & 1023;
                int row = rem >> 3, seg = rem & 7;
                const __half* src = (piece ? Al : Ah) + (size_t)(m0 + row)*1024 + k0 + seg*8;
                uint32_t sa = sbase + (bufw + (piece ? OFF_AL : OFF_AH) + row*STRW + seg*4)*4;
                cp16(sa, src);
            } else {
                int t2 = task - 2048;
                int piece = t2 >> 9, rem = t2 & 511;
                int row = rem >> 3, seg = rem & 7;
                const __half* src = (piece ? Bl : Bh) + (size_t)(n0 + row)*1024 + k0 + seg*8;
                uint32_t sa = sbase + (bufw + (piece ? OFF_BL : OFF_BH) + row*STRW + seg*4)*4;
                cp16(sa, src);
            }
        }
        CP_COMMIT();
    };

    issue(0);
    for (int ch = 0; ch < 16; ch++) {
        if (ch + 1 < 16) { issue(ch + 1); CP_WAIT1(); }
        else             { CP_WAIT0(); }
        __syncthreads();

        uint32_t bufw = (uint32_t)(ch & 1) * BUFW;
        const uint32_t* AsH = sg + bufw + OFF_AH;
        const uint32_t* AsL = sg + bufw + OFF_AL;
        const uint32_t* BsH = sg + bufw + OFF_BH;
        const uint32_t* BsL = sg + bufw + OFF_BL;

        #pragma unroll
        for (int s = 0; s < 4; s++) {
            uint32_t aH[2][4], aL[2][4];
            #pragma unroll
            for (int mt = 0; mt < 2; mt++) {
                int o = (wm*32 + mt*16 + g)*STRW + s*8 + t4;
                aH[mt][0] = AsH[o];           aH[mt][1] = AsH[o + 8*STRW];
                aH[mt][2] = AsH[o + 4];       aH[mt][3] = AsH[o + 8*STRW + 4];
                aL[mt][0] = AsL[o];           aL[mt][1] = AsL[o + 8*STRW];
                aL[mt][2] = AsL[o + 4];       aL[mt][3] = AsL[o + 8*STRW + 4];
            }
            #pragma unroll
            for (int nt = 0; nt < 4; nt++) {
                int o = (wn*32 + nt*8 + g)*STRW + s*8 + t4;
                uint32_t bh0 = BsH[o], bh1 = BsH[o + 4];
                uint32_t bl0 = BsL[o], bl1 = BsL[o + 4];
                #pragma unroll
                for (int mt = 0; mt < 2; mt++) {
                    mma_f16(acc[mt][nt], aH[mt], bh0, bh1);
                    mma_f16(acc[mt][nt], aH[mt], bl0, bl1);
                    mma_f16(acc[mt][nt], aL[mt], bh0, bh1);
                }
            }
        }
        __syncthreads();
    }

    #pragma unroll
    for (int mt = 0; mt < 2; mt++) {
        int r0 = m0 + wm*32 + mt*16 + g;
        int r1 = r0 + 8;
        #pragma unroll
        for (int nt = 0; nt < 4; nt++) {
            int col = n0 + wn*32 + nt*8 + t4*2;
            float2 v0 = make_float2(acc[mt][nt][0], acc[mt][nt][1]);
            float2 v1 = make_float2(acc[mt][nt][2], acc[mt][nt][3]);
            if (Res) {
                float2 q0 = *(const float2*)(Res + (size_t)r0*N + col);
                float2 q1 = *(const float2*)(Res + (size_t)r1*N + col);
                v0.x += q0.x; v0.y += q0.y;
                v1.x += q1.x; v1.y += q1.y;
            }
            *(float2*)(C + (size_t)r0*N + col) = v0;
            *(float2*)(C + (size_t)r1*N + col) = v1;
        }
    }
}

// ============================================================
// RMSNorm -> fp16 hi/lo
// ============================================================
__global__ __launch_bounds__(256) void rmsnorm_kernel(
    const float* __restrict__ x, const float* __restrict__ w,
    __half* __restrict__ out_h, __half* __restrict__ out_l)
{
    int row = blockIdx.x;
    int tid = threadIdx.x;
    const float4* xr = (const float4*)(x + (size_t)row*EMB);
    float4 v = xr[tid];
    float ss = v.x*v.x + v.y*v.y + v.z*v.z + v.w*v.w;
    #pragma unroll
    for (int o = 16; o > 0; o >>= 1) ss += __shfl_xor_sync(0xffffffffu, ss, o);
    __shared__ float wsum[8];
    if ((tid & 31) == 0) wsum[tid >> 5] = ss;
    __syncthreads();
    if (tid < 8) {
        float t = wsum[tid];
        #pragma unroll
        for (int o = 4; o > 0; o >>= 1) t += __shfl_xor_sync(0xffu, t, o);
        if (tid == 0) wsum[0] = t;
    }
    __syncthreads();
    float inv = rsqrtf(wsum[0] * (1.0f/EMB) + EPS);
    float4 wv = ((const float4*)w)[tid];
    float4 o4;
    o4.x = v.x*inv*wv.x; o4.y = v.y*inv*wv.y;
    o4.z = v.z*inv*wv.z; o4.w = v.w*inv*wv.w;
    __half hx, lx, hy, ly, hz, lz, hw, lw;
    split_f16(o4.x, hx, lx);  split_f16(o4.y, hy, ly);
    split_f16(o4.z, hz, lz);  split_f16(o4.w, hw, lw);
    __half2 h01 = __halves2half2(hx, hy), h23 = __halves2half2(hz, hw);
    __half2 l01 = __halves2half2(lx, ly), l23 = __halves2half2(lz, lw);
    uint2 hp, lp;
    hp.x = *(uint32_t*)&h01; hp.y = *(uint32_t*)&h23;
    lp.x = *(uint32_t*)&l01; lp.y = *(uint32_t*)&l23;
    *(uint2*)(out_h + (size_t)row*EMB + tid*4) = hp;
    *(uint2*)(out_l + (size_t)row*EMB + tid*4) = lp;
}

// ============================================================
// prep_qk: RoPE + (q: scale 1/8) + fp16 split -> [bh][s][64]
// ============================================================
__global__ __launch_bounds__(256) void prep_qk_kernel(
    const float* __restrict__ qkv, const float* __restrict__ cosb,
    const float* __restrict__ sinb,
    __half* __restrict__ qh, __half* __restrict__ ql,
    __half* __restrict__ kh, __half* __restrict__ kl)
{
    int idx = blockIdx.x * blockDim.x + threadIdx.x;   // 2^22
    int d  = idx & 31;
    int h  = (idx >> 5) & 15;
    int m  = (idx >> 9) & 4095;
    int t  = idx >> 21;                 // 0=q, 1=k
    int s  = m & (SEQ - 1);
    int b  = m >> 11;
    const float* p = qkv + (size_t)m*QKVN + t*EMB + h*HD;
    float x0 = p[d], x1 = p[d + 32];
    float c0 = cosb[s*HD + d],      c1 = cosb[s*HD + d + 32];
    float s0 = sinb[s*HD + d],      s1 = sinb[s*HD + d + 32];
    float r0 = c0*x0 + s0*x1;
    float r1 = c1*x1 + s1*x0;
    if (t == 0) { r0 *= 0.125f; r1 *= 0.125f; }
    __half* oh = (t ? kh : qh);
    __half* ol = (t ? kl : ql);
    size_t base = ((size_t)(b*NH + h)*SEQ + s)*HD;
    __half h0, l0, h1, l1;
    split_f16(r0, h0, l0);
    split_f16(r1, h1, l1);
    oh[base + d]      = h0;  ol[base + d]      = l0;
    oh[base + d + 32] = h1;  ol[base + d + 32] = l1;
}

// ============================================================
// prep_v: tiled transpose V -> [bh][d][s], fp16 (hi only)
// ============================================================
__global__ __launch_bounds__(256) void prep_v_kernel(
    const float* __restrict__ qkv, __half* __restrict__ vth)
{
    __shared__ float ts[64*65];
    int st = blockIdx.x * 64, h = blockIdx.y, b = blockIdx.z;
    int tid = threadIdx.x;
    int row = tid >> 2, seg = tid & 3;
    const float* src = qkv + (size_t)(b*SEQ + st + row)*QKVN + 2*EMB + h*HD;
    #pragma unroll
    for (int j = 0; j < 4; j++) {
        int f4 = seg*4 + j;
        float4 v = *(const float4*)(src + f4*4);
        ts[row*65 + f4*4+0] = v.x; ts[row*65 + f4*4+1] = v.y;
        ts[row*65 + f4*4+2] = v.z; ts[row*65 + f4*4+3] = v.w;
    }
    __syncthreads();
    int d = tid >> 2, ss = tid & 3;
    __half hv[16];
    #pragma unroll
    for (int j = 0; j < 16; j++)
        hv[j] = __float2half_rn(ts[(ss*16 + j)*65 + d]);
    size_t ob = ((size_t)((b*NH + h)*HD) + d)*SEQ + st + ss*16;
    #pragma unroll
    for (int j = 0; j < 4; j++) {
        __half2 a = __halves2half2(hv[4*j], hv[4*j+1]);
        __half2 c = __halves2half2(hv[4*j+2], hv[4*j+3]);
        uint2 pk; pk.x = *(uint32_t*)&a; pk.y = *(uint32_t*)&c;
        *(uint2*)(vth + ob + 4*j) = pk;
    }
}

// ============================================================
// Tensor-core causal flash attention
//  QK^T: 3x fp16 hi/lo;  PV: single-pass fp16 (P,V hi only)
// ============================================================
#define QROWS 128
#define KSTRW 36
#define QSZW  (QROWS*KSTRW)
#define KSZW  (64*KSTRW)
#define F_QH 0
#define F_QL QSZW
#define F_KH (2*QSZW)
#define F_KL (2*QSZW + 2*KSZW)
#define F_VH (2*QSZW + 4*KSZW)
#define FLASH_SMEM ((2*QSZW + 6*KSZW)*4)   // 92160 bytes

__global__ __launch_bounds__(256, 1) void flash_mma_kernel(
    const __half* __restrict__ Qh, const __half* __restrict__ Ql,
    const __half* __restrict__ Kh, const __half* __restrict__ Kl,
    const __half* __restrict__ Vth,
    __half* __restrict__ attn_h, __half* __restrict__ attn_l)
{
    extern __shared__ __align__(16) uint32_t sf[];
    uint32_t sbase = smem_u32(sf);
    int tid = threadIdx.x, lane = tid & 31, wid = tid >> 5;
    int g = lane >> 2, t4 = lane & 3;
    int qt = (gridDim.x - 1) - blockIdx.x;
    int h = blockIdx.y, b = blockIdx.z;
    int bh = b*NH + h;
    int q0 = qt * QROWS;
    int nkt = 2*(qt + 1);

    const __half* gQh = Qh  + (size_t)bh*SEQ*HD;
    const __half* gQl = Ql  + (size_t)bh*SEQ*HD;
    const __half* gKh = Kh  + (size_t)bh*SEQ*HD;
    const __half* gKl = Kl  + (size_t)bh*SEQ*HD;
    const __half* gVh = Vth + (size_t)bh*HD*SEQ;

    auto issueKV = [&](int kt) {
        int k0 = kt * 64;
        uint32_t bufw = (uint32_t)(kt & 1) * KSZW;
        #pragma unroll
        for (int i = 0; i < 4; i++) {            // K hi/lo: 1024 tasks
            int task = tid + i*256;
            int piece = task >> 9, rem = task & 511;
            int row = rem >> 3, seg = rem & 7;
            const __half* src = (piece ? gKl : gKh) + (size_t)(k0 + row)*HD + seg*8;
            uint32_t dst = sbase + (((piece ? F_KL : F_KH) + bufw) + row*KSTRW + seg*4)*4;
            cp16(dst, src);
        }
        #pragma unroll
        for (int i = 0; i < 2; i++) {            // V hi: 512 tasks
            int task = tid + i*256;
            int row = task >> 3, seg = task & 7;
            const __half* src = gVh + (size_t)row*SEQ + k0 + seg*8;
            uint32_t dst = sbase + ((F_VH + bufw) + row*KSTRW + seg*4)*4;
            cp16(dst, src);
        }
    };

    #pragma unroll
    for (int i = 0; i < 8; i++) {
        int task = tid + i*256;
        int piece = task >> 10, rem = task & 1023;
        int row = rem >> 3, seg = rem & 7;
        const __half* src = (piece ? gQl : gQh) + (size_t)(q0 + row)*HD + seg*8;
        uint32_t dst = sbase + ((piece ? F_QL : F_QH) + row*KSTRW + seg*4)*4;
        cp16(dst, src);
    }
    issueKV(0);
    CP_COMMIT();

    float m0 = -INFINITY, m1 = -INFINITY, l0 = 0.f, l1 = 0.f;
    float o[8][4];
    #pragma unroll
    for (int dt = 0; dt < 8; dt++)
        #pragma unroll
        for (int e = 0; e < 4; e++) o[dt][e] = 0.f;

    const uint32_t* QhS = sf + F_QH;
    const uint32_t* QlS = sf + F_QL;
    int qrow = (wid*16 + g) * KSTRW;

    for (int kt = 0; kt < nkt; kt++) {
        if (kt + 1 < nkt) { issueKV(kt + 1); CP_COMMIT(); CP_WAIT1(); }
        else              { CP_WAIT0(); }
        __syncthreads();

        uint32_t bufw = (uint32_t)(kt & 1) * KSZW;
        const uint32_t* KhS = sf + F_KH + bufw;
        const uint32_t* KlS = sf + F_KL + bufw;
        const uint32_t* VhS = sf + F_VH + bufw;

        // ---- scores: 3x fp16 hi/lo ----
        float sc[8][4];
        #pragma unroll
        for (int nt = 0; nt < 8; nt++)
            #pragma unroll
            for (int e = 0; e < 4; e++) sc[nt][e] = 0.f;

        #pragma unroll
        for (int s = 0; s < 4; s++) {
            int qo = qrow + s*8 + t4;
            uint32_t aH[4] = { QhS[qo], QhS[qo + 8*KSTRW], QhS[qo + 4], QhS[qo + 8*KSTRW + 4] };
            uint32_t aL[4] = { QlS[qo], QlS[qo + 8*KSTRW], QlS[qo + 4], QlS[qo + 8*KSTRW + 4] };
            #pragma unroll
            for (int nt = 0; nt < 8; nt++) {
                int ko = (nt*8 + g)*KSTRW + s*8 + t4;
                uint32_t bh0 = KhS[ko], bh1 = KhS[ko + 4];
                uint32_t bl0 = KlS[ko], bl1 = KlS[ko + 4];
                mma_f16(sc[nt], aH, bh0, bh1);
                mma_f16(sc[nt], aH, bl0, bl1);
                mma_f16(sc[nt], aL, bh0, bh1);
            }
        }

        if (kt >= 2*qt) {
            int cb = kt*64;
            int r0 = q0 + wid*16 + g, r1 = r0 + 8;
            #pragma unroll
            for (int nt = 0; nt < 8; nt++) {
                int c0 = cb + nt*8 + 2*t4;
                if (c0     > r0) sc[nt][0] = -INFINITY;
                if (c0 + 1 > r0) sc[nt][1] = -INFINITY;
                if (c0     > r1) sc[nt][2] = -INFINITY;
                if (c0 + 1 > r1) sc[nt][3] = -INFINITY;
            }
        }

        float mt0 = -INFINITY, mt1 = -INFINITY;
        #pragma unroll
        for (int nt = 0; nt < 8; nt++) {
            mt0 = fmaxf(mt0, fmaxf(sc[nt][0], sc[nt][1]));
            mt1 = fmaxf(mt1, fmaxf(sc[nt][2], sc[nt][3]));
        }
        mt0 = fmaxf(mt0, __shfl_xor_sync(0xffffffffu, mt0, 1));
        mt0 = fmaxf(mt0, __shfl_xor_sync(0xffffffffu, mt0, 2));
        mt1 = fmaxf(mt1, __shfl_xor_sync(0xffffffffu, mt1, 1));
        mt1 = fmaxf(mt1, __shfl_xor_sync(0xffffffffu, mt1, 2));
        float mn0 = fmaxf(m0, mt0), mn1 = fmaxf(m1, mt1);
        float corr0 = __expf(m0 - mn0), corr1 = __expf(m1 - mn1);
        m0 = mn0; m1 = mn1;

        float ls0 = 0.f, ls1 = 0.f;
        uint32_t phA[8], phB[8];
        #pragma unroll
        for (int nt = 0; nt < 8; nt++) {
            float p0 = __expf(sc[nt][0] - mn0);
            float p1 = __expf(sc[nt][1] - mn0);
            float p2 = __expf(sc[nt][2] - mn1);
            float p3 = __expf(sc[nt][3] - mn1);
            ls0 += p0 + p1;  ls1 += p2 + p3;
            __half2 hA = __floats2half2_rn(p0, p1);
            __half2 hB = __floats2half2_rn(p2, p3);
            phA[nt] = *(uint32_t*)&hA;
            phB[nt] = *(uint32_t*)&hB;
        }
        ls0 += __shfl_xor_sync(0xffffffffu, ls0, 1);
        ls0 += __shfl_xor_sync(0xffffffffu, ls0, 2);
        ls1 += __shfl_xor_sync(0xffffffffu, ls1, 1);
        ls1 += __shfl_xor_sync(0xffffffffu, ls1, 2);
        l0 = l0*corr0 + ls0;
        l1 = l1*corr1 + ls1;
        #pragma unroll
        for (int dt = 0; dt < 8; dt++) {
            o[dt][0] *= corr0; o[dt][1] *= corr0;
            o[dt][2] *= corr1; o[dt][3] *= corr1;
        }

        // ---- PV: single-pass fp16 ----
        #pragma unroll
        for (int kk = 0; kk < 4; kk++) {
            uint32_t aH[4] = { phA[2*kk], phB[2*kk], phA[2*kk+1], phB[2*kk+1] };
            #pragma unroll
            for (int dt = 0; dt < 8; dt++) {
                int vo = (dt*8 + g)*KSTRW + kk*8 + t4;
                uint32_t vh0 = VhS[vo], vh1 = VhS[vo + 4];
                mma_f16(o[dt], aH, vh0, vh1);
            }
        }
        __syncthreads();
    }

    float il0 = 1.0f / l0, il1 = 1.0f / l1;
    int r0g = b*SEQ + q0 + wid*16 + g;
    int r1g = r0g + 8;
    int cbase = h*HD;
    #pragma unroll
    for (int dt = 0; dt < 8; dt++) {
        int c = cbase + dt*8 + 2*t4;
        float v0 = o[dt][0]*il0, v1 = o[dt][1]*il0;
        float v2 = o[dt][2]*il1, v3 = o[dt][3]*il1;
        __half h0,l0h,h1,l1h,h2,l2h,h3,l3h;
        split_f16(v0, h0, l0h);  split_f16(v1, h1, l1h);
        split_f16(v2, h2, l2h);  split_f16(v3, h3, l3h);
        __half2 ha = __halves2half2(h0, h1), la = __halves2half2(l0h, l1h);
        __half2 hb = __halves2half2(h2, h3), lb = __halves2half2(l2h, l3h);
        *(uint32_t*)(attn_h + (size_t)r0g*EMB + c) = *(uint32_t*)&ha;
        *(uint32_t*)(attn_l + (size_t)r0g*EMB + c) = *(uint32_t*)&la;
        *(uint32_t*)(attn_h + (size_t)r1g*EMB + c) = *(uint32_t*)&hb;
        *(uint32_t*)(attn_l + (size_t)r1g*EMB + c) = *(uint32_t*)&lb;
    }
}

// ============================================================
// launch
// ============================================================
extern "C" void kernel_launch(void* const* d_in, const int* in_sizes, int n_in,
                              void* d_out, int out_size)
{
    const float* emb  = (const float*)d_in[0];
    const float* cosb = (const float*)d_in[1];
    const float* sinb = (const float*)d_in[2];
    const float* nw   = (const float*)d_in[3];
    const float* qkvw = (const float*)d_in[4];
    const float* ow   = (const float*)d_in[5];
    float* out = (float*)d_out;

    float* qkv;
    __half *nh, *nl, *ah, *al, *wqh, *wql, *woh, *wol;
    __half *qh, *ql, *kh, *kl, *vth;
    cudaGetSymbolAddress((void**)&qkv, g_qkv);
    cudaGetSymbolAddress((void**)&nh,  g_nrm_h);
    cudaGetSymbolAddress((void**)&nl,  g_nrm_l);
    cudaGetSymbolAddress((void**)&ah,  g_att_h);
    cudaGetSymbolAddress((void**)&al,  g_att_l);
    cudaGetSymbolAddress((void**)&wqh, g_wqkv_h);
    cudaGetSymbolAddress((void**)&wql, g_wqkv_l);
    cudaGetSymbolAddress((void**)&woh, g_wo_h);
    cudaGetSymbolAddress((void**)&wol, g_wo_l);
    cudaGetSymbolAddress((void**)&qh,  g_qh);
    cudaGetSymbolAddress((void**)&ql,  g_ql);
    cudaGetSymbolAddress((void**)&kh,  g_kh);
    cudaGetSymbolAddress((void**)&kl,  g_kl);
    cudaGetSymbolAddress((void**)&vth, g_vth);

    cudaFuncSetAttribute(gemm_f16_kernel,
        cudaFuncAttributeMaxDynamicSharedMemorySize, GEMM_SMEM);
    cudaFuncSetAttribute(flash_mma_kernel,
        cudaFuncAttributeMaxDynamicSharedMemorySize, FLASH_SMEM);

    conv_f16_kernel<<<(QKVN*EMB/4)/256, 256>>>(qkvw, wqh, wql);
    conv_f16_kernel<<<(EMB*EMB/4)/256, 256>>>(ow, woh, wol);
    rmsnorm_kernel<<<MROWS, 256>>>(emb, nw, nh, nl);
    gemm_f16_kernel<<<dim3(QKVN/64, MROWS/128), 256, GEMM_SMEM>>>(
        nh, nl, wqh, wql, nullptr, qkv, QKVN);
    prep_qk_kernel<<<(2*MROWS*NH*32)/256, 256>>>(qkv, cosb, sinb, qh, ql, kh, kl);
    prep_v_kernel<<<dim3(SEQ/64, NH, BATCH), 256>>>(qkv, vth);
    flash_mma_kernel<<<dim3(SEQ/QROWS, NH, BATCH), 256, FLASH_SMEM>>>(
        qh, ql, kh, kl, vth, ah, al);
    gemm_f16_kernel<<<dim3(EMB/64, MROWS/128), 256, GEMM_SMEM>>>(
        ah, al, woh, wol, emb, out, EMB);
}

// round 13
// speedup vs baseline: 2.0649x; 1.2765x over previous
#include <cuda_runtime.h>
#include <cuda_fp16.h>
#include <math.h>
#include <stdint.h>

#define EMB   1024
#define NH    16
#define HD    64
#define SEQ   2048
#define BATCH 2
#define MROWS (BATCH*SEQ)     // 4096
#define QKVN  (3*EMB)         // 3072
#define EPS   1.1920929e-07f

// ---- scratch (no allocations allowed) ----
__device__ float  g_qkv[(size_t)MROWS*QKVN];
__device__ __half g_nrm_h[(size_t)MROWS*EMB];
__device__ __half g_nrm_l[(size_t)MROWS*EMB];
__device__ __half g_att_h[(size_t)MROWS*EMB];
__device__ __half g_att_l[(size_t)MROWS*EMB];
__device__ __half g_wqkv_h[(size_t)QKVN*EMB];
__device__ __half g_wo_h[(size_t)EMB*EMB];
__device__ __half g_qh[(size_t)BATCH*NH*SEQ*HD];
__device__ __half g_ql[(size_t)BATCH*NH*SEQ*HD];
__device__ __half g_kh[(size_t)BATCH*NH*SEQ*HD];
__device__ __half g_vth[(size_t)BATCH*NH*HD*SEQ];

// ============================================================
// helpers
// ============================================================
__device__ __forceinline__ uint32_t smem_u32(const void* p) {
    uint32_t a;
    asm("{ .reg .u64 t; cvta.to.shared.u64 t, %1; cvt.u32.u64 %0, t; }" : "=r"(a) : "l"(p));
    return a;
}
__device__ __forceinline__ void split_f16(float x, __half& h, __half& l) {
    h = __float2half_rn(x);
    l = __float2half_rn(x - __half2float(h));
}
__device__ __forceinline__ void mma_f16(float* c, const uint32_t* a,
                                        uint32_t b0, uint32_t b1) {
    asm volatile(
        "mma.sync.aligned.m16n8k16.row.col.f32.f16.f16.f32 "
        "{%0,%1,%2,%3}, {%4,%5,%6,%7}, {%8,%9}, {%0,%1,%2,%3};"
        : "+f"(c[0]), "+f"(c[1]), "+f"(c[2]), "+f"(c[3])
        : "r"(a[0]), "r"(a[1]), "r"(a[2]), "r"(a[3]), "r"(b0), "r"(b1));
}
__device__ __forceinline__ void cp16(uint32_t sdst, const void* gsrc) {
    asm volatile("cp.async.cg.shared.global [%0], [%1], 16;" :: "r"(sdst), "l"(gsrc));
}
#define CP_COMMIT() asm volatile("cp.async.commit_group;")
#define CP_WAIT1()  asm volatile("cp.async.wait_group 1;")
#define CP_WAIT0()  asm volatile("cp.async.wait_group 0;")

// ============================================================
// weight fp16 hi conversion (lo pass dropped)
// ============================================================
__global__ __launch_bounds__(256) void conv_hi_kernel(
    const float* __restrict__ x, __half* __restrict__ hi)
{
    int i = blockIdx.x * 256 + threadIdx.x;
    float4 v = ((const float4*)x)[i];
    __half2 h01 = __floats2half2_rn(v.x, v.y);
    __half2 h23 = __floats2half2_rn(v.z, v.w);
    uint2 hp;
    hp.x = *(uint32_t*)&h01; hp.y = *(uint32_t*)&h23;
    *(uint2*)(hi + (size_t)i*4) = hp;
}

// ============================================================
// GEMM via mma.sync fp16 (2x: (Ah+Al)*Bh)
// CTA tile 128(M) x 64(N), K-chunk 64, double-buffered, 2 CTAs/SM
// ============================================================
#define STRW  36                      // words (u32) per smem row (72 halfs)
#define TWA   (128*STRW)
#define TWB   (64*STRW)
#define BUFW  (2*TWA + TWB)           // Ah, Al, Bh
#define OFF_AH 0
#define OFF_AL TWA
#define OFF_BH (2*TWA)
#define GEMM_SMEM (2*BUFW*4)          // 92160 bytes

__global__ __launch_bounds__(256, 2) void gemm_f16_kernel(
    const __half* __restrict__ Ah, const __half* __restrict__ Al,
    const __half* __restrict__ Bh,
    const float* __restrict__ Res, float* __restrict__ C, int N)
{
    extern __shared__ __align__(16) uint32_t sg[];
    uint32_t sbase = smem_u32(sg);
    int tid = threadIdx.x;
    int m0 = blockIdx.y * 128, n0 = blockIdx.x * 64;
    int lane = tid & 31, wid = tid >> 5;
    int g = lane >> 2, t4 = lane & 3;
    int wm = wid & 3, wn = wid >> 2;

    float acc[2][4][4];
    #pragma unroll
    for (int mt = 0; mt < 2; mt++)
        #pragma unroll
        for (int nt = 0; nt < 4; nt++)
            #pragma unroll
            for (int r = 0; r < 4; r++) acc[mt][nt][r] = 0.0f;

    auto issue = [&](int ch) {
        int k0 = ch * 64;
        uint32_t bufw = (uint32_t)(ch & 1) * BUFW;
        #pragma unroll
        for (int i = 0; i < 10; i++) {           // 2560 tasks (8 halfs each)
            int task = tid + i * 256;
            if (task < 2048) {                   // A hi/lo
                int piece = task >> 10, rem = task & 1023;
                int row = rem >> 3, seg = rem & 7;
                const __half* src = (piece ? Al : Ah) + (size_t)(m0 + row)*1024 + k0 + seg*8;
                uint32_t sa = sbase + (bufw + (piece ? OFF_AL : OFF_AH) + row*STRW + seg*4)*4;
                cp16(sa, src);
            } else {                             // B hi
                int t2 = task - 2048;            // 0..511
                int row = t2 >> 3, seg = t2 & 7;
                const __half* src = Bh + (size_t)(n0 + row)*1024 + k0 + seg*8;
                uint32_t sa = sbase + (bufw + OFF_BH + row*STRW + seg*4)*4;
                cp16(sa, src);
            }
        }
        CP_COMMIT();
    };

    issue(0);
    for (int ch = 0; ch < 16; ch++) {
        if (ch + 1 < 16) { issue(ch + 1); CP_WAIT1(); }
        else             { CP_WAIT0(); }
        __syncthreads();

        uint32_t bufw = (uint32_t)(ch & 1) * BUFW;
        const uint32_t* AsH = sg + bufw + OFF_AH;
        const uint32_t* AsL = sg + bufw + OFF_AL;
        const uint32_t* BsH = sg + bufw + OFF_BH;

        #pragma unroll
        for (int s = 0; s < 4; s++) {
            uint32_t aH[2][4], aL[2][4];
            #pragma unroll
            for (int mt = 0; mt < 2; mt++) {
                int o = (wm*32 + mt*16 + g)*STRW + s*8 + t4;
                aH[mt][0] = AsH[o];           aH[mt][1] = AsH[o + 8*STRW];
                aH[mt][2] = AsH[o + 4];       aH[mt][3] = AsH[o + 8*STRW + 4];
                aL[mt][0] = AsL[o];           aL[mt][1] = AsL[o + 8*STRW];
                aL[mt][2] = AsL[o + 4];       aL[mt][3] = AsL[o + 8*STRW + 4];
            }
            #pragma unroll
            for (int nt = 0; nt < 4; nt++) {
                int o = (wn*32 + nt*8 + g)*STRW + s*8 + t4;
                uint32_t bh0 = BsH[o], bh1 = BsH[o + 4];
                #pragma unroll
                for (int mt = 0; mt < 2; mt++) {
                    mma_f16(acc[mt][nt], aH[mt], bh0, bh1);
                    mma_f16(acc[mt][nt], aL[mt], bh0, bh1);
                }
            }
        }
        __syncthreads();
    }

    #pragma unroll
    for (int mt = 0; mt < 2; mt++) {
        int r0 = m0 + wm*32 + mt*16 + g;
        int r1 = r0 + 8;
        #pragma unroll
        for (int nt = 0; nt < 4; nt++) {
            int col = n0 + wn*32 + nt*8 + t4*2;
            float2 v0 = make_float2(acc[mt][nt][0], acc[mt][nt][1]);
            float2 v1 = make_float2(acc[mt][nt][2], acc[mt][nt][3]);
            if (Res) {
                float2 q0 = *(const float2*)(Res + (size_t)r0*N + col);
                float2 q1 = *(const float2*)(Res + (size_t)r1*N + col);
                v0.x += q0.x; v0.y += q0.y;
                v1.x += q1.x; v1.y += q1.y;
            }
            *(float2*)(C + (size_t)r0*N + col) = v0;
            *(float2*)(C + (size_t)r1*N + col) = v1;
        }
    }
}

// ============================================================
// RMSNorm -> fp16 hi/lo
// ============================================================
__global__ __launch_bounds__(256) void rmsnorm_kernel(
    const float* __restrict__ x, const float* __restrict__ w,
    __half* __restrict__ out_h, __half* __restrict__ out_l)
{
    int row = blockIdx.x;
    int tid = threadIdx.x;
    const float4* xr = (const float4*)(x + (size_t)row*EMB);
    float4 v = xr[tid];
    float ss = v.x*v.x + v.y*v.y + v.z*v.z + v.w*v.w;
    #pragma unroll
    for (int o = 16; o > 0; o >>= 1) ss += __shfl_xor_sync(0xffffffffu, ss, o);
    __shared__ float wsum[8];
    if ((tid & 31) == 0) wsum[tid >> 5] = ss;
    __syncthreads();
    if (tid < 8) {
        float t = wsum[tid];
        #pragma unroll
        for (int o = 4; o > 0; o >>= 1) t += __shfl_xor_sync(0xffu, t, o);
        if (tid == 0) wsum[0] = t;
    }
    __syncthreads();
    float inv = rsqrtf(wsum[0] * (1.0f/EMB) + EPS);
    float4 wv = ((const float4*)w)[tid];
    float4 o4;
    o4.x = v.x*inv*wv.x; o4.y = v.y*inv*wv.y;
    o4.z = v.z*inv*wv.z; o4.w = v.w*inv*wv.w;
    __half hx, lx, hy, ly, hz, lz, hw, lw;
    split_f16(o4.x, hx, lx);  split_f16(o4.y, hy, ly);
    split_f16(o4.z, hz, lz);  split_f16(o4.w, hw, lw);
    __half2 h01 = __halves2half2(hx, hy), h23 = __halves2half2(hz, hw);
    __half2 l01 = __halves2half2(lx, ly), l23 = __halves2half2(lz, lw);
    uint2 hp, lp;
    hp.x = *(uint32_t*)&h01; hp.y = *(uint32_t*)&h23;
    lp.x = *(uint32_t*)&l01; lp.y = *(uint32_t*)&l23;
    *(uint2*)(out_h + (size_t)row*EMB + tid*4) = hp;
    *(uint2*)(out_l + (size_t)row*EMB + tid*4) = lp;
}

// ============================================================
// prep_qk: RoPE + (q: scale 1/8) + fp16 split -> [bh][s][64]
//  q: hi+lo; k: hi only
// ============================================================
__global__ __launch_bounds__(256) void prep_qk_kernel(
    const float* __restrict__ qkv, const float* __restrict__ cosb,
    const float* __restrict__ sinb,
    __half* __restrict__ qh, __half* __restrict__ ql,
    __half* __restrict__ kh)
{
    int idx = blockIdx.x * blockDim.x + threadIdx.x;   // 2^22
    int d  = idx & 31;
    int h  = (idx >> 5) & 15;
    int m  = (idx >> 9) & 4095;
    int t  = idx >> 21;                 // 0=q, 1=k
    int s  = m & (SEQ - 1);
    int b  = m >> 11;
    const float* p = qkv + (size_t)m*QKVN + t*EMB + h*HD;
    float x0 = p[d], x1 = p[d + 32];
    float c0 = cosb[s*HD + d],      c1 = cosb[s*HD + d + 32];
    float s0 = sinb[s*HD + d],      s1 = sinb[s*HD + d + 32];
    float r0 = c0*x0 + s0*x1;
    float r1 = c1*x1 + s1*x0;
    size_t base = ((size_t)(b*NH + h)*SEQ + s)*HD;
    if (t == 0) {
        r0 *= 0.125f; r1 *= 0.125f;
        __half h0, l0, h1, l1;
        split_f16(r0, h0, l0);
        split_f16(r1, h1, l1);
        qh[base + d]      = h0;  ql[base + d]      = l0;
        qh[base + d + 32] = h1;  ql[base + d + 32] = l1;
    } else {
        kh[base + d]      = __float2half_rn(r0);
        kh[base + d + 32] = __float2half_rn(r1);
    }
}

// ============================================================
// prep_v: tiled transpose V -> [bh][d][s], fp16 (hi only)
// ============================================================
__global__ __launch_bounds__(256) void prep_v_kernel(
    const float* __restrict__ qkv, __half* __restrict__ vth)
{
    __shared__ float ts[64*65];
    int st = blockIdx.x * 64, h = blockIdx.y, b = blockIdx.z;
    int tid = threadIdx.x;
    int row = tid >> 2, seg = tid & 3;
    const float* src = qkv + (size_t)(b*SEQ + st + row)*QKVN + 2*EMB + h*HD;
    #pragma unroll
    for (int j = 0; j < 4; j++) {
        int f4 = seg*4 + j;
        float4 v = *(const float4*)(src + f4*4);
        ts[row*65 + f4*4+0] = v.x; ts[row*65 + f4*4+1] = v.y;
        ts[row*65 + f4*4+2] = v.z; ts[row*65 + f4*4+3] = v.w;
    }
    __syncthreads();
    int d = tid >> 2, ss = tid & 3;
    __half hv[16];
    #pragma unroll
    for (int j = 0; j < 16; j++)
        hv[j] = __float2half_rn(ts[(ss*16 + j)*65 + d]);
    size_t ob = ((size_t)((b*NH + h)*HD) + d)*SEQ + st + ss*16;
    #pragma unroll
    for (int j = 0; j < 4; j++) {
        __half2 a = __halves2half2(hv[4*j], hv[4*j+1]);
        __half2 c = __halves2half2(hv[4*j+2], hv[4*j+3]);
        uint2 pk; pk.x = *(uint32_t*)&a; pk.y = *(uint32_t*)&c;
        *(uint2*)(vth + ob + 4*j) = pk;
    }
}

// ============================================================
// Tensor-core causal flash attention
//  QK^T: 2x fp16 ((Qh+Ql)*Kh);  PV: single-pass fp16
// ============================================================
#define QROWS 128
#define KSTRW 36
#define QSZW  (QROWS*KSTRW)
#define KSZW  (64*KSTRW)
#define F_QH 0
#define F_QL QSZW
#define F_KH (2*QSZW)                  // + buf*KSZW (2 bufs)
#define F_VH (2*QSZW + 2*KSZW)         // + buf*KSZW (2 bufs)
#define FLASH_SMEM ((2*QSZW + 4*KSZW)*4)   // 73728 bytes

__global__ __launch_bounds__(256, 1) void flash_mma_kernel(
    const __half* __restrict__ Qh, const __half* __restrict__ Ql,
    const __half* __restrict__ Kh, const __half* __restrict__ Vth,
    __half* __restrict__ attn_h, __half* __restrict__ attn_l)
{
    extern __shared__ __align__(16) uint32_t sf[];
    uint32_t sbase = smem_u32(sf);
    int tid = threadIdx.x, lane = tid & 31, wid = tid >> 5;
    int g = lane >> 2, t4 = lane & 3;
    int qt = (gridDim.x - 1) - blockIdx.x;
    int h = blockIdx.y, b = blockIdx.z;
    int bh = b*NH + h;
    int q0 = qt * QROWS;
    int nkt = 2*(qt + 1);

    const __half* gQh = Qh  + (size_t)bh*SEQ*HD;
    const __half* gQl = Ql  + (size_t)bh*SEQ*HD;
    const __half* gKh = Kh  + (size_t)bh*SEQ*HD;
    const __half* gVh = Vth + (size_t)bh*HD*SEQ;

    auto issueKV = [&](int kt) {
        int k0 = kt * 64;
        uint32_t bufw = (uint32_t)(kt & 1) * KSZW;
        #pragma unroll
        for (int i = 0; i < 2; i++) {            // K hi: 512 tasks
            int task = tid + i*256;
            int row = task >> 3, seg = task & 7;
            const __half* src = gKh + (size_t)(k0 + row)*HD + seg*8;
            uint32_t dst = sbase + ((F_KH + bufw) + row*KSTRW + seg*4)*4;
            cp16(dst, src);
        }
        #pragma unroll
        for (int i = 0; i < 2; i++) {            // V hi: 512 tasks
            int task = tid + i*256;
            int row = task >> 3, seg = task & 7;
            const __half* src = gVh + (size_t)row*SEQ + k0 + seg*8;
            uint32_t dst = sbase + ((F_VH + bufw) + row*KSTRW + seg*4)*4;
            cp16(dst, src);
        }
    };

    #pragma unroll
    for (int i = 0; i < 8; i++) {
        int task = tid + i*256;
        int piece = task >> 10, rem = task & 1023;
        int row = rem >> 3, seg = rem & 7;
        const __half* src = (piece ? gQl : gQh) + (size_t)(q0 + row)*HD + seg*8;
        uint32_t dst = sbase + ((piece ? F_QL : F_QH) + row*KSTRW + seg*4)*4;
        cp16(dst, src);
    }
    issueKV(0);
    CP_COMMIT();

    float m0 = -INFINITY, m1 = -INFINITY, l0 = 0.f, l1 = 0.f;
    float o[8][4];
    #pragma unroll
    for (int dt = 0; dt < 8; dt++)
        #pragma unroll
        for (int e = 0; e < 4; e++) o[dt][e] = 0.f;

    const uint32_t* QhS = sf + F_QH;
    const uint32_t* QlS = sf + F_QL;
    int qrow = (wid*16 + g) * KSTRW;

    for (int kt = 0; kt < nkt; kt++) {
        if (kt + 1 < nkt) { issueKV(kt + 1); CP_COMMIT(); CP_WAIT1(); }
        else              { CP_WAIT0(); }
        __syncthreads();

        uint32_t bufw = (uint32_t)(kt & 1) * KSZW;
        const uint32_t* KhS = sf + F_KH + bufw;
        const uint32_t* VhS = sf + F_VH + bufw;

        // ---- scores: 2x fp16 ((Qh+Ql)*Kh) ----
        float sc[8][4];
        #pragma unroll
        for (int nt = 0; nt < 8; nt++)
            #pragma unroll
            for (int e = 0; e < 4; e++) sc[nt][e] = 0.f;

        #pragma unroll
        for (int s = 0; s < 4; s++) {
            int qo = qrow + s*8 + t4;
            uint32_t aH[4] = { QhS[qo], QhS[qo + 8*KSTRW], QhS[qo + 4], QhS[qo + 8*KSTRW + 4] };
            uint32_t aL[4] = { QlS[qo], QlS[qo + 8*KSTRW], QlS[qo + 4], QlS[qo + 8*KSTRW + 4] };
            #pragma unroll
            for (int nt = 0; nt < 8; nt++) {
                int ko = (nt*8 + g)*KSTRW + s*8 + t4;
                uint32_t bh0 = KhS[ko], bh1 = KhS[ko + 4];
                mma_f16(sc[nt], aH, bh0, bh1);
                mma_f16(sc[nt], aL, bh0, bh1);
            }
        }

        if (kt >= 2*qt) {
            int cb = kt*64;
            int r0 = q0 + wid*16 + g, r1 = r0 + 8;
            #pragma unroll
            for (int nt = 0; nt < 8; nt++) {
                int c0 = cb + nt*8 + 2*t4;
                if (c0     > r0) sc[nt][0] = -INFINITY;
                if (c0 + 1 > r0) sc[nt][1] = -INFINITY;
                if (c0     > r1) sc[nt][2] = -INFINITY;
                if (c0 + 1 > r1) sc[nt][3] = -INFINITY;
            }
        }

        float mt0 = -INFINITY, mt1 = -INFINITY;
        #pragma unroll
        for (int nt = 0; nt < 8; nt++) {
            mt0 = fmaxf(mt0, fmaxf(sc[nt][0], sc[nt][1]));
            mt1 = fmaxf(mt1, fmaxf(sc[nt][2], sc[nt][3]));
        }
        mt0 = fmaxf(mt0, __shfl_xor_sync(0xffffffffu, mt0, 1));
        mt0 = fmaxf(mt0, __shfl_xor_sync(0xffffffffu, mt0, 2));
        mt1 = fmaxf(mt1, __shfl_xor_sync(0xffffffffu, mt1, 1));
        mt1 = fmaxf(mt1, __shfl_xor_sync(0xffffffffu, mt1, 2));
        float mn0 = fmaxf(m0, mt0), mn1 = fmaxf(m1, mt1);
        float corr0 = __expf(m0 - mn0), corr1 = __expf(m1 - mn1);
        m0 = mn0; m1 = mn1;

        float ls0 = 0.f, ls1 = 0.f;
        uint32_t phA[8], phB[8];
        #pragma unroll
        for (int nt = 0; nt < 8; nt++) {
            float p0 = __expf(sc[nt][0] - mn0);
            float p1 = __expf(sc[nt][1] - mn0);
            float p2 = __expf(sc[nt][2] - mn1);
            float p3 = __expf(sc[nt][3] - mn1);
            ls0 += p0 + p1;  ls1 += p2 + p3;
            __half2 hA = __floats2half2_rn(p0, p1);
            __half2 hB = __floats2half2_rn(p2, p3);
            phA[nt] = *(uint32_t*)&hA;
            phB[nt] = *(uint32_t*)&hB;
        }
        ls0 += __shfl_xor_sync(0xffffffffu, ls0, 1);
        ls0 += __shfl_xor_sync(0xffffffffu, ls0, 2);
        ls1 += __shfl_xor_sync(0xffffffffu, ls1, 1);
        ls1 += __shfl_xor_sync(0xffffffffu, ls1, 2);
        l0 = l0*corr0 + ls0;
        l1 = l1*corr1 + ls1;
        #pragma unroll
        for (int dt = 0; dt < 8; dt++) {
            o[dt][0] *= corr0; o[dt][1] *= corr0;
            o[dt][2] *= corr1; o[dt][3] *= corr1;
        }

        // ---- PV: single-pass fp16 ----
        #pragma unroll
        for (int kk = 0; kk < 4; kk++) {
            uint32_t aH[4] = { phA[2*kk], phB[2*kk], phA[2*kk+1], phB[2*kk+1] };
            #pragma unroll
            for (int dt = 0; dt < 8; dt++) {
                int vo = (dt*8 + g)*KSTRW + kk*8 + t4;
                uint32_t vh0 = VhS[vo], vh1 = VhS[vo + 4];
                mma_f16(o[dt], aH, vh0, vh1);
            }
        }
        __syncthreads();
    }

    float il0 = 1.0f / l0, il1 = 1.0f / l1;
    int r0g = b*SEQ + q0 + wid*16 + g;
    int r1g = r0g + 8;
    int cbase = h*HD;
    #pragma unroll
    for (int dt = 0; dt < 8; dt++) {
        int c = cbase + dt*8 + 2*t4;
        float v0 = o[dt][0]*il0, v1 = o[dt][1]*il0;
        float v2 = o[dt][2]*il1, v3 = o[dt][3]*il1;
        __half h0,l0h,h1,l1h,h2,l2h,h3,l3h;
        split_f16(v0, h0, l0h);  split_f16(v1, h1, l1h);
        split_f16(v2, h2, l2h);  split_f16(v3, h3, l3h);
        __half2 ha = __halves2half2(h0, h1), la = __halves2half2(l0h, l1h);
        __half2 hb = __halves2half2(h2, h3), lb = __halves2half2(l2h, l3h);
        *(uint32_t*)(attn_h + (size_t)r0g*EMB + c) = *(uint32_t*)&ha;
        *(uint32_t*)(attn_l + (size_t)r0g*EMB + c) = *(uint32_t*)&la;
        *(uint32_t*)(attn_h + (size_t)r1g*EMB + c) = *(uint32_t*)&hb;
        *(uint32_t*)(attn_l + (size_t)r1g*EMB + c) = *(uint32_t*)&lb;
    }
}

// ============================================================
// launch
// ============================================================
extern "C" void kernel_launch(void* const* d_in, const int* in_sizes, int n_in,
                              void* d_out, int out_size)
{
    const float* emb  = (const float*)d_in[0];
    const float* cosb = (const float*)d_in[1];
    const float* sinb = (const float*)d_in[2];
    const float* nw   = (const float*)d_in[3];
    const float* qkvw = (const float*)d_in[4];
    const float* ow   = (const float*)d_in[5];
    float* out = (float*)d_out;

    float* qkv;
    __half *nh, *nl, *ah, *al, *wqh, *woh;
    __half *qh, *ql, *kh, *vth;
    cudaGetSymbolAddress((void**)&qkv, g_qkv);
    cudaGetSymbolAddress((void**)&nh,  g_nrm_h);
    cudaGetSymbolAddress((void**)&nl,  g_nrm_l);
    cudaGetSymbolAddress((void**)&ah,  g_att_h);
    cudaGetSymbolAddress((void**)&al,  g_att_l);
    cudaGetSymbolAddress((void**)&wqh, g_wqkv_h);
    cudaGetSymbolAddress((void**)&woh, g_wo_h);
    cudaGetSymbolAddress((void**)&qh,  g_qh);
    cudaGetSymbolAddress((void**)&ql,  g_ql);
    cudaGetSymbolAddress((void**)&kh,  g_kh);
    cudaGetSymbolAddress((void**)&vth, g_vth);

    cudaFuncSetAttribute(gemm_f16_kernel,
        cudaFuncAttributeMaxDynamicSharedMemorySize, GEMM_SMEM);
    cudaFuncSetAttribute(flash_mma_kernel,
        cudaFuncAttributeMaxDynamicSharedMemorySize, FLASH_SMEM);

    conv_hi_kernel<<<(QKVN*EMB/4)/256, 256>>>(qkvw, wqh);
    conv_hi_kernel<<<(EMB*EMB/4)/256, 256>>>(ow, woh);
    rmsnorm_kernel<<<MROWS, 256>>>(emb, nw, nh, nl);
    gemm_f16_kernel<<<dim3(QKVN/64, MROWS/128), 256, GEMM_SMEM>>>(
        nh, nl, wqh, nullptr, qkv, QKVN);
    prep_qk_kernel<<<(2*MROWS*NH*32)/256, 256>>>(qkv, cosb, sinb, qh, ql, kh);
    prep_v_kernel<<<dim3(SEQ/64, NH, BATCH), 256>>>(qkv, vth);
    flash_mma_kernel<<<dim3(SEQ/QROWS, NH, BATCH), 256, FLASH_SMEM>>>(
        qh, ql, kh, vth, ah, al);
    gemm_f16_kernel<<<dim3(EMB/64, MROWS/128), 256, GEMM_SMEM>>>(
        ah, al, woh, emb, out, EMB);
}

// round 14
// speedup vs baseline: 2.8896x; 1.3994x over previous
#include <cuda_runtime.h>
#include <cuda_fp16.h>
#include <math.h>
#include <stdint.h>

#define EMB   1024
#define NH    16
#define HD    64
#define SEQ   2048
#define BATCH 2
#define MROWS (BATCH*SEQ)     // 4096
#define QKVN  (3*EMB)         // 3072
#define EPS   1.1920929e-07f

// ---- scratch (no allocations allowed) ----
__device__ float  g_qkv[(size_t)MROWS*QKVN];
__device__ __half g_nrm_h[(size_t)MROWS*EMB];
__device__ __half g_att_h[(size_t)MROWS*EMB];
__device__ __half g_wqkv_h[(size_t)QKVN*EMB];
__device__ __half g_wo_h[(size_t)EMB*EMB];
__device__ __half g_qh[(size_t)BATCH*NH*SEQ*HD];
__device__ __half g_kh[(size_t)BATCH*NH*SEQ*HD];
__device__ __half g_vth[(size_t)BATCH*NH*HD*SEQ];

// ============================================================
// helpers
// ============================================================
__device__ __forceinline__ uint32_t smem_u32(const void* p) {
    uint32_t a;
    asm("{ .reg .u64 t; cvta.to.shared.u64 t, %1; cvt.u32.u64 %0, t; }" : "=r"(a) : "l"(p));
    return a;
}
__device__ __forceinline__ void mma_f16(float* c, const uint32_t* a,
                                        uint32_t b0, uint32_t b1) {
    asm volatile(
        "mma.sync.aligned.m16n8k16.row.col.f32.f16.f16.f32 "
        "{%0,%1,%2,%3}, {%4,%5,%6,%7}, {%8,%9}, {%0,%1,%2,%3};"
        : "+f"(c[0]), "+f"(c[1]), "+f"(c[2]), "+f"(c[3])
        : "r"(a[0]), "r"(a[1]), "r"(a[2]), "r"(a[3]), "r"(b0), "r"(b1));
}
__device__ __forceinline__ void cp16(uint32_t sdst, const void* gsrc) {
    asm volatile("cp.async.cg.shared.global [%0], [%1], 16;" :: "r"(sdst), "l"(gsrc));
}
#define CP_COMMIT() asm volatile("cp.async.commit_group;")
#define CP_WAIT1()  asm volatile("cp.async.wait_group 1;")
#define CP_WAIT0()  asm volatile("cp.async.wait_group 0;")

// ============================================================
// weight fp16 conversion
// ============================================================
__global__ __launch_bounds__(256) void conv_hi_kernel(
    const float* __restrict__ x, __half* __restrict__ hi)
{
    int i = blockIdx.x * 256 + threadIdx.x;
    float4 v = ((const float4*)x)[i];
    __half2 h01 = __floats2half2_rn(v.x, v.y);
    __half2 h23 = __floats2half2_rn(v.z, v.w);
    uint2 hp;
    hp.x = *(uint32_t*)&h01; hp.y = *(uint32_t*)&h23;
    *(uint2*)(hi + (size_t)i*4) = hp;
}

// ============================================================
// GEMM via mma.sync fp16 (single pass, fp32 accumulate)
// CTA tile 128(M) x 64(N), K-chunk 64, double-buffered, 2 CTAs/SM
// ============================================================
#define STRW  36                      // words (u32) per smem row (72 halfs)
#define TWA   (128*STRW)
#define TWB   (64*STRW)
#define BUFW  (TWA + TWB)             // Ah, Bh
#define OFF_AH 0
#define OFF_BH TWA
#define GEMM_SMEM (2*BUFW*4)          // 55296 bytes

__global__ __launch_bounds__(256, 2) void gemm_f16_kernel(
    const __half* __restrict__ Ah, const __half* __restrict__ Bh,
    const float* __restrict__ Res, float* __restrict__ C, int N)
{
    extern __shared__ __align__(16) uint32_t sg[];
    uint32_t sbase = smem_u32(sg);
    int tid = threadIdx.x;
    int m0 = blockIdx.y * 128, n0 = blockIdx.x * 64;
    int lane = tid & 31, wid = tid >> 5;
    int g = lane >> 2, t4 = lane & 3;
    int wm = wid & 3, wn = wid >> 2;

    float acc[2][4][4];
    #pragma unroll
    for (int mt = 0; mt < 2; mt++)
        #pragma unroll
        for (int nt = 0; nt < 4; nt++)
            #pragma unroll
            for (int r = 0; r < 4; r++) acc[mt][nt][r] = 0.0f;

    auto issue = [&](int ch) {
        int k0 = ch * 64;
        uint32_t bufw = (uint32_t)(ch & 1) * BUFW;
        #pragma unroll
        for (int i = 0; i < 6; i++) {            // 1536 tasks (8 halfs each)
            int task = tid + i * 256;
            if (task < 1024) {                   // A hi
                int row = task >> 3, seg = task & 7;
                const __half* src = Ah + (size_t)(m0 + row)*1024 + k0 + seg*8;
                uint32_t sa = sbase + (bufw + OFF_AH + row*STRW + seg*4)*4;
                cp16(sa, src);
            } else {                             // B hi
                int t2 = task - 1024;            // 0..511
                int row = t2 >> 3, seg = t2 & 7;
                const __half* src = Bh + (size_t)(n0 + row)*1024 + k0 + seg*8;
                uint32_t sa = sbase + (bufw + OFF_BH + row*STRW + seg*4)*4;
                cp16(sa, src);
            }
        }
        CP_COMMIT();
    };

    issue(0);
    for (int ch = 0; ch < 16; ch++) {
        if (ch + 1 < 16) { issue(ch + 1); CP_WAIT1(); }
        else             { CP_WAIT0(); }
        __syncthreads();

        uint32_t bufw = (uint32_t)(ch & 1) * BUFW;
        const uint32_t* AsH = sg + bufw + OFF_AH;
        const uint32_t* BsH = sg + bufw + OFF_BH;

        #pragma unroll
        for (int s = 0; s < 4; s++) {
            uint32_t aH[2][4];
            #pragma unroll
            for (int mt = 0; mt < 2; mt++) {
                int o = (wm*32 + mt*16 + g)*STRW + s*8 + t4;
                aH[mt][0] = AsH[o];           aH[mt][1] = AsH[o + 8*STRW];
                aH[mt][2] = AsH[o + 4];       aH[mt][3] = AsH[o + 8*STRW + 4];
            }
            #pragma unroll
            for (int nt = 0; nt < 4; nt++) {
                int o = (wn*32 + nt*8 + g)*STRW + s*8 + t4;
                uint32_t bh0 = BsH[o], bh1 = BsH[o + 4];
                #pragma unroll
                for (int mt = 0; mt < 2; mt++)
                    mma_f16(acc[mt][nt], aH[mt], bh0, bh1);
            }
        }
        __syncthreads();
    }

    #pragma unroll
    for (int mt = 0; mt < 2; mt++) {
        int r0 = m0 + wm*32 + mt*16 + g;
        int r1 = r0 + 8;
        #pragma unroll
        for (int nt = 0; nt < 4; nt++) {
            int col = n0 + wn*32 + nt*8 + t4*2;
            float2 v0 = make_float2(acc[mt][nt][0], acc[mt][nt][1]);
            float2 v1 = make_float2(acc[mt][nt][2], acc[mt][nt][3]);
            if (Res) {
                float2 q0 = *(const float2*)(Res + (size_t)r0*N + col);
                float2 q1 = *(const float2*)(Res + (size_t)r1*N + col);
                v0.x += q0.x; v0.y += q0.y;
                v1.x += q1.x; v1.y += q1.y;
            }
            *(float2*)(C + (size_t)r0*N + col) = v0;
            *(float2*)(C + (size_t)r1*N + col) = v1;
        }
    }
}

// ============================================================
// RMSNorm -> fp16
// ============================================================
__global__ __launch_bounds__(256) void rmsnorm_kernel(
    const float* __restrict__ x, const float* __restrict__ w,
    __half* __restrict__ out_h)
{
    int row = blockIdx.x;
    int tid = threadIdx.x;
    const float4* xr = (const float4*)(x + (size_t)row*EMB);
    float4 v = xr[tid];
    float ss = v.x*v.x + v.y*v.y + v.z*v.z + v.w*v.w;
    #pragma unroll
    for (int o = 16; o > 0; o >>= 1) ss += __shfl_xor_sync(0xffffffffu, ss, o);
    __shared__ float wsum[8];
    if ((tid & 31) == 0) wsum[tid >> 5] = ss;
    __syncthreads();
    if (tid < 8) {
        float t = wsum[tid];
        #pragma unroll
        for (int o = 4; o > 0; o >>= 1) t += __shfl_xor_sync(0xffu, t, o);
        if (tid == 0) wsum[0] = t;
    }
    __syncthreads();
    float inv = rsqrtf(wsum[0] * (1.0f/EMB) + EPS);
    float4 wv = ((const float4*)w)[tid];
    __half2 h01 = __floats2half2_rn(v.x*inv*wv.x, v.y*inv*wv.y);
    __half2 h23 = __floats2half2_rn(v.z*inv*wv.z, v.w*inv*wv.w);
    uint2 hp;
    hp.x = *(uint32_t*)&h01; hp.y = *(uint32_t*)&h23;
    *(uint2*)(out_h + (size_t)row*EMB + tid*4) = hp;
}

// ============================================================
// prep_qk: RoPE + (q: scale 1/8) + fp16 -> [bh][s][64]
// ============================================================
__global__ __launch_bounds__(256) void prep_qk_kernel(
    const float* __restrict__ qkv, const float* __restrict__ cosb,
    const float* __restrict__ sinb,
    __half* __restrict__ qh, __half* __restrict__ kh)
{
    int idx = blockIdx.x * blockDim.x + threadIdx.x;   // 2^22
    int d  = idx & 31;
    int h  = (idx >> 5) & 15;
    int m  = (idx >> 9) & 4095;
    int t  = idx >> 21;                 // 0=q, 1=k
    int s  = m & (SEQ - 1);
    int b  = m >> 11;
    const float* p = qkv + (size_t)m*QKVN + t*EMB + h*HD;
    float x0 = p[d], x1 = p[d + 32];
    float c0 = cosb[s*HD + d],      c1 = cosb[s*HD + d + 32];
    float s0 = sinb[s*HD + d],      s1 = sinb[s*HD + d + 32];
    float r0 = c0*x0 + s0*x1;
    float r1 = c1*x1 + s1*x0;
    if (t == 0) { r0 *= 0.125f; r1 *= 0.125f; }
    __half* oh = (t ? kh : qh);
    size_t base = ((size_t)(b*NH + h)*SEQ + s)*HD;
    oh[base + d]      = __float2half_rn(r0);
    oh[base + d + 32] = __float2half_rn(r1);
}

// ============================================================
// prep_v: tiled transpose V -> [bh][d][s], fp16
// ============================================================
__global__ __launch_bounds__(256) void prep_v_kernel(
    const float* __restrict__ qkv, __half* __restrict__ vth)
{
    __shared__ float ts[64*65];
    int st = blockIdx.x * 64, h = blockIdx.y, b = blockIdx.z;
    int tid = threadIdx.x;
    int row = tid >> 2, seg = tid & 3;
    const float* src = qkv + (size_t)(b*SEQ + st + row)*QKVN + 2*EMB + h*HD;
    #pragma unroll
    for (int j = 0; j < 4; j++) {
        int f4 = seg*4 + j;
        float4 v = *(const float4*)(src + f4*4);
        ts[row*65 + f4*4+0] = v.x; ts[row*65 + f4*4+1] = v.y;
        ts[row*65 + f4*4+2] = v.z; ts[row*65 + f4*4+3] = v.w;
    }
    __syncthreads();
    int d = tid >> 2, ss = tid & 3;
    __half hv[16];
    #pragma unroll
    for (int j = 0; j < 16; j++)
        hv[j] = __float2half_rn(ts[(ss*16 + j)*65 + d]);
    size_t ob = ((size_t)((b*NH + h)*HD) + d)*SEQ + st + ss*16;
    #pragma unroll
    for (int j = 0; j < 4; j++) {
        __half2 a = __halves2half2(hv[4*j], hv[4*j+1]);
        __half2 c = __halves2half2(hv[4*j+2], hv[4*j+3]);
        uint2 pk; pk.x = *(uint32_t*)&a; pk.y = *(uint32_t*)&c;
        *(uint2*)(vth + ob + 4*j) = pk;
    }
}

// ============================================================
// Tensor-core causal flash attention (single-pass fp16 QK & PV)
// ============================================================
#define QROWS 128
#define KSTRW 36
#define QSZW  (QROWS*KSTRW)
#define KSZW  (64*KSTRW)
#define F_QH 0
#define F_KH QSZW                      // + buf*KSZW (2 bufs)
#define F_VH (QSZW + 2*KSZW)           // + buf*KSZW (2 bufs)
#define FLASH_SMEM ((QSZW + 4*KSZW)*4)   // 55296 bytes

__global__ __launch_bounds__(256, 1) void flash_mma_kernel(
    const __half* __restrict__ Qh, const __half* __restrict__ Kh,
    const __half* __restrict__ Vth, __half* __restrict__ attn_h)
{
    extern __shared__ __align__(16) uint32_t sf[];
    uint32_t sbase = smem_u32(sf);
    int tid = threadIdx.x, lane = tid & 31, wid = tid >> 5;
    int g = lane >> 2, t4 = lane & 3;
    int qt = (gridDim.x - 1) - blockIdx.x;
    int h = blockIdx.y, b = blockIdx.z;
    int bh = b*NH + h;
    int q0 = qt * QROWS;
    int nkt = 2*(qt + 1);

    const __half* gQh = Qh  + (size_t)bh*SEQ*HD;
    const __half* gKh = Kh  + (size_t)bh*SEQ*HD;
    const __half* gVh = Vth + (size_t)bh*HD*SEQ;

    auto issueKV = [&](int kt) {
        int k0 = kt * 64;
        uint32_t bufw = (uint32_t)(kt & 1) * KSZW;
        #pragma unroll
        for (int i = 0; i < 2; i++) {            // K hi: 512 tasks
            int task = tid + i*256;
            int row = task >> 3, seg = task & 7;
            const __half* src = gKh + (size_t)(k0 + row)*HD + seg*8;
            uint32_t dst = sbase + ((F_KH + bufw) + row*KSTRW + seg*4)*4;
            cp16(dst, src);
        }
        #pragma unroll
        for (int i = 0; i < 2; i++) {            // V hi: 512 tasks
            int task = tid + i*256;
            int row = task >> 3, seg = task & 7;
            const __half* src = gVh + (size_t)row*SEQ + k0 + seg*8;
            uint32_t dst = sbase + ((F_VH + bufw) + row*KSTRW + seg*4)*4;
            cp16(dst, src);
        }
    };

    #pragma unroll
    for (int i = 0; i < 4; i++) {                // Q hi: 1024 tasks
        int task = tid + i*256;
        int row = task >> 3, seg = task & 7;
        const __half* src = gQh + (size_t)(q0 + row)*HD + seg*8;
        uint32_t dst = sbase + (F_QH + row*KSTRW + seg*4)*4;
        cp16(dst, src);
    }
    issueKV(0);
    CP_COMMIT();

    float m0 = -INFINITY, m1 = -INFINITY, l0 = 0.f, l1 = 0.f;
    float o[8][4];
    #pragma unroll
    for (int dt = 0; dt < 8; dt++)
        #pragma unroll
        for (int e = 0; e < 4; e++) o[dt][e] = 0.f;

    const uint32_t* QhS = sf + F_QH;
    int qrow = (wid*16 + g) * KSTRW;

    for (int kt = 0; kt < nkt; kt++) {
        if (kt + 1 < nkt) { issueKV(kt + 1); CP_COMMIT(); CP_WAIT1(); }
        else              { CP_WAIT0(); }
        __syncthreads();

        uint32_t bufw = (uint32_t)(kt & 1) * KSZW;
        const uint32_t* KhS = sf + F_KH + bufw;
        const uint32_t* VhS = sf + F_VH + bufw;

        // ---- scores: single-pass fp16 ----
        float sc[8][4];
        #pragma unroll
        for (int nt = 0; nt < 8; nt++)
            #pragma unroll
            for (int e = 0; e < 4; e++) sc[nt][e] = 0.f;

        #pragma unroll
        for (int s = 0; s < 4; s++) {
            int qo = qrow + s*8 + t4;
            uint32_t aH[4] = { QhS[qo], QhS[qo + 8*KSTRW], QhS[qo + 4], QhS[qo + 8*KSTRW + 4] };
            #pragma unroll
            for (int nt = 0; nt < 8; nt++) {
                int ko = (nt*8 + g)*KSTRW + s*8 + t4;
                mma_f16(sc[nt], aH, KhS[ko], KhS[ko + 4]);
            }
        }

        if (kt >= 2*qt) {
            int cb = kt*64;
            int r0 = q0 + wid*16 + g, r1 = r0 + 8;
            #pragma unroll
            for (int nt = 0; nt < 8; nt++) {
                int c0 = cb + nt*8 + 2*t4;
                if (c0     > r0) sc[nt][0] = -INFINITY;
                if (c0 + 1 > r0) sc[nt][1] = -INFINITY;
                if (c0     > r1) sc[nt][2] = -INFINITY;
                if (c0 + 1 > r1) sc[nt][3] = -INFINITY;
            }
        }

        float mt0 = -INFINITY, mt1 = -INFINITY;
        #pragma unroll
        for (int nt = 0; nt < 8; nt++) {
            mt0 = fmaxf(mt0, fmaxf(sc[nt][0], sc[nt][1]));
            mt1 = fmaxf(mt1, fmaxf(sc[nt][2], sc[nt][3]));
        }
        mt0 = fmaxf(mt0, __shfl_xor_sync(0xffffffffu, mt0, 1));
        mt0 = fmaxf(mt0, __shfl_xor_sync(0xffffffffu, mt0, 2));
        mt1 = fmaxf(mt1, __shfl_xor_sync(0xffffffffu, mt1, 1));
        mt1 = fmaxf(mt1, __shfl_xor_sync(0xffffffffu, mt1, 2));
        float mn0 = fmaxf(m0, mt0), mn1 = fmaxf(m1, mt1);
        float corr0 = __expf(m0 - mn0), corr1 = __expf(m1 - mn1);
        m0 = mn0; m1 = mn1;

        float ls0 = 0.f, ls1 = 0.f;
        uint32_t phA[8], phB[8];
        #pragma unroll
        for (int nt = 0; nt < 8; nt++) {
            float p0 = __expf(sc[nt][0] - mn0);
            float p1 = __expf(sc[nt][1] - mn0);
            float p2 = __expf(sc[nt][2] - mn1);
            float p3 = __expf(sc[nt][3] - mn1);
            ls0 += p0 + p1;  ls1 += p2 + p3;
            __half2 hA = __floats2half2_rn(p0, p1);
            __half2 hB = __floats2half2_rn(p2, p3);
            phA[nt] = *(uint32_t*)&hA;
            phB[nt] = *(uint32_t*)&hB;
        }
        ls0 += __shfl_xor_sync(0xffffffffu, ls0, 1);
        ls0 += __shfl_xor_sync(0xffffffffu, ls0, 2);
        ls1 += __shfl_xor_sync(0xffffffffu, ls1, 1);
        ls1 += __shfl_xor_sync(0xffffffffu, ls1, 2);
        l0 = l0*corr0 + ls0;
        l1 = l1*corr1 + ls1;
        #pragma unroll
        for (int dt = 0; dt < 8; dt++) {
            o[dt][0] *= corr0; o[dt][1] *= corr0;
            o[dt][2] *= corr1; o[dt][3] *= corr1;
        }

        // ---- PV: single-pass fp16 ----
        #pragma unroll
        for (int kk = 0; kk < 4; kk++) {
            uint32_t aH[4] = { phA[2*kk], phB[2*kk], phA[2*kk+1], phB[2*kk+1] };
            #pragma unroll
            for (int dt = 0; dt < 8; dt++) {
                int vo = (dt*8 + g)*KSTRW + kk*8 + t4;
                mma_f16(o[dt], aH, VhS[vo], VhS[vo + 4]);
            }
        }
        __syncthreads();
    }

    float il0 = 1.0f / l0, il1 = 1.0f / l1;
    int r0g = b*SEQ + q0 + wid*16 + g;
    int r1g = r0g + 8;
    int cbase = h*HD;
    #pragma unroll
    for (int dt = 0; dt < 8; dt++) {
        int c = cbase + dt*8 + 2*t4;
        __half2 ha = __floats2half2_rn(o[dt][0]*il0, o[dt][1]*il0);
        __half2 hb = __floats2half2_rn(o[dt][2]*il1, o[dt][3]*il1);
        *(uint32_t*)(attn_h + (size_t)r0g*EMB + c) = *(uint32_t*)&ha;
        *(uint32_t*)(attn_h + (size_t)r1g*EMB + c) = *(uint32_t*)&hb;
    }
}

// ============================================================
// launch
// ============================================================
extern "C" void kernel_launch(void* const* d_in, const int* in_sizes, int n_in,
                              void* d_out, int out_size)
{
    const float* emb  = (const float*)d_in[0];
    const float* cosb = (const float*)d_in[1];
    const float* sinb = (const float*)d_in[2];
    const float* nw   = (const float*)d_in[3];
    const float* qkvw = (const float*)d_in[4];
    const float* ow   = (const float*)d_in[5];
    float* out = (float*)d_out;

    float* qkv;
    __half *nh, *ah, *wqh, *woh, *qh, *kh, *vth;
    cudaGetSymbolAddress((void**)&qkv, g_qkv);
    cudaGetSymbolAddress((void**)&nh,  g_nrm_h);
    cudaGetSymbolAddress((void**)&ah,  g_att_h);
    cudaGetSymbolAddress((void**)&wqh, g_wqkv_h);
    cudaGetSymbolAddress((void**)&woh, g_wo_h);
    cudaGetSymbolAddress((void**)&qh,  g_qh);
    cudaGetSymbolAddress((void**)&kh,  g_kh);
    cudaGetSymbolAddress((void**)&vth, g_vth);

    cudaFuncSetAttribute(gemm_f16_kernel,
        cudaFuncAttributeMaxDynamicSharedMemorySize, GEMM_SMEM);
    cudaFuncSetAttribute(flash_mma_kernel,
        cudaFuncAttributeMaxDynamicSharedMemorySize, FLASH_SMEM);

    conv_hi_kernel<<<(QKVN*EMB/4)/256, 256>>>(qkvw, wqh);
    conv_hi_kernel<<<(EMB*EMB/4)/256, 256>>>(ow, woh);
    rmsnorm_kernel<<<MROWS, 256>>>(emb, nw, nh);
    gemm_f16_kernel<<<dim3(QKVN/64, MROWS/128), 256, GEMM_SMEM>>>(
        nh, wqh, nullptr, qkv, QKVN);
    prep_qk_kernel<<<(2*MROWS*NH*32)/256, 256>>>(qkv, cosb, sinb, qh, kh);
    prep_v_kernel<<<dim3(SEQ/64, NH, BATCH), 256>>>(qkv, vth);
    flash_mma_kernel<<<dim3(SEQ/QROWS, NH, BATCH), 256, FLASH_SMEM>>>(
        qh, kh, vth, ah);
    gemm_f16_kernel<<<dim3(EMB/64, MROWS/128), 256, GEMM_SMEM>>>(
        ah, woh, emb, out, EMB);
}

// round 15
// speedup vs baseline: 3.1055x; 1.0747x over previous
#include <cuda_runtime.h>
#include <cuda_fp16.h>
#include <math.h>
#include <stdint.h>

#define EMB   1024
#define NH    16
#define HD    64
#define SEQ   2048
#define BATCH 2
#define MROWS (BATCH*SEQ)     // 4096
#define QKVN  (3*EMB)         // 3072
#define EPS   1.1920929e-07f

// ---- scratch (no allocations allowed) ----
__device__ float  g_qkv[(size_t)MROWS*QKVN];
__device__ __half g_nrm_h[(size_t)MROWS*EMB];
__device__ __half g_att_h[(size_t)MROWS*EMB];
__device__ __half g_wqkv_h[(size_t)QKVN*EMB];
__device__ __half g_wo_h[(size_t)EMB*EMB];
__device__ __half g_qh[(size_t)BATCH*NH*SEQ*HD];
__device__ __half g_kh[(size_t)BATCH*NH*SEQ*HD];
__device__ __half g_vth[(size_t)BATCH*NH*HD*SEQ];

// ============================================================
// helpers
// ============================================================
__device__ __forceinline__ uint32_t smem_u32(const void* p) {
    uint32_t a;
    asm("{ .reg .u64 t; cvta.to.shared.u64 t, %1; cvt.u32.u64 %0, t; }" : "=r"(a) : "l"(p));
    return a;
}
__device__ __forceinline__ void mma_f16(float* c, const uint32_t* a,
                                        uint32_t b0, uint32_t b1) {
    asm volatile(
        "mma.sync.aligned.m16n8k16.row.col.f32.f16.f16.f32 "
        "{%0,%1,%2,%3}, {%4,%5,%6,%7}, {%8,%9}, {%0,%1,%2,%3};"
        : "+f"(c[0]), "+f"(c[1]), "+f"(c[2]), "+f"(c[3])
        : "r"(a[0]), "r"(a[1]), "r"(a[2]), "r"(a[3]), "r"(b0), "r"(b1));
}
__device__ __forceinline__ void cp16(uint32_t sdst, const void* gsrc) {
    asm volatile("cp.async.cg.shared.global [%0], [%1], 16;" :: "r"(sdst), "l"(gsrc));
}
#define CP_COMMIT() asm volatile("cp.async.commit_group;")
#define CP_WAIT1()  asm volatile("cp.async.wait_group 1;")
#define CP_WAIT0()  asm volatile("cp.async.wait_group 0;")

// ============================================================
// weight fp16 conversion
// ============================================================
__global__ __launch_bounds__(256) void conv_hi_kernel(
    const float* __restrict__ x, __half* __restrict__ hi)
{
    int i = blockIdx.x * 256 + threadIdx.x;
    float4 v = ((const float4*)x)[i];
    __half2 h01 = __floats2half2_rn(v.x, v.y);
    __half2 h23 = __floats2half2_rn(v.z, v.w);
    uint2 hp;
    hp.x = *(uint32_t*)&h01; hp.y = *(uint32_t*)&h23;
    *(uint2*)(hi + (size_t)i*4) = hp;
}

// ============================================================
// GEMM via mma.sync fp16 (single pass, fp32 accumulate)
// CTA tile 128(M) x 128(N), K-chunk 64, double-buffered, 2 CTAs/SM
// ============================================================
#define STRW  36                      // words (u32) per smem row (72 halfs)
#define TWA   (128*STRW)              // 4608 words (A or B tile)
#define BUFW  (2*TWA)                 // Ah, Bh
#define OFF_AH 0
#define OFF_BH TWA
#define GEMM_SMEM (2*BUFW*4)          // 147456 bytes

__global__ __launch_bounds__(256, 2) void gemm_f16_kernel(
    const __half* __restrict__ Ah, const __half* __restrict__ Bh,
    const float* __restrict__ Res, float* __restrict__ C, int N)
{
    extern __shared__ __align__(16) uint32_t sg[];
    uint32_t sbase = smem_u32(sg);
    int tid = threadIdx.x;
    int m0 = blockIdx.y * 128, n0 = blockIdx.x * 128;
    int lane = tid & 31, wid = tid >> 5;
    int g = lane >> 2, t4 = lane & 3;
    int wm = wid & 3, wn = wid >> 2;

    float acc[2][8][4];
    #pragma unroll
    for (int mt = 0; mt < 2; mt++)
        #pragma unroll
        for (int nt = 0; nt < 8; nt++)
            #pragma unroll
            for (int r = 0; r < 4; r++) acc[mt][nt][r] = 0.0f;

    auto issue = [&](int ch) {
        int k0 = ch * 64;
        uint32_t bufw = (uint32_t)(ch & 1) * BUFW;
        #pragma unroll
        for (int i = 0; i < 8; i++) {            // 2048 tasks (8 halfs each)
            int task = tid + i * 256;
            int piece = task >> 10;              // 0 = A, 1 = B
            int rem = task & 1023;
            int row = rem >> 3, seg = rem & 7;
            const __half* src = (piece ? Bh : Ah) + (size_t)((piece ? n0 : m0) + row)*1024 + k0 + seg*8;
            uint32_t sa = sbase + (bufw + (piece ? OFF_BH : OFF_AH) + row*STRW + seg*4)*4;
            cp16(sa, src);
        }
        CP_COMMIT();
    };

    issue(0);
    for (int ch = 0; ch < 16; ch++) {
        if (ch + 1 < 16) { issue(ch + 1); CP_WAIT1(); }
        else             { CP_WAIT0(); }
        __syncthreads();

        uint32_t bufw = (uint32_t)(ch & 1) * BUFW;
        const uint32_t* AsH = sg + bufw + OFF_AH;
        const uint32_t* BsH = sg + bufw + OFF_BH;

        #pragma unroll
        for (int s = 0; s < 4; s++) {
            uint32_t aH[2][4];
            #pragma unroll
            for (int mt = 0; mt < 2; mt++) {
                int o = (wm*32 + mt*16 + g)*STRW + s*8 + t4;
                aH[mt][0] = AsH[o];           aH[mt][1] = AsH[o + 8*STRW];
                aH[mt][2] = AsH[o + 4];       aH[mt][3] = AsH[o + 8*STRW + 4];
            }
            #pragma unroll
            for (int nt = 0; nt < 8; nt++) {
                int o = (wn*64 + nt*8 + g)*STRW + s*8 + t4;
                uint32_t bh0 = BsH[o], bh1 = BsH[o + 4];
                #pragma unroll
                for (int mt = 0; mt < 2; mt++)
                    mma_f16(acc[mt][nt], aH[mt], bh0, bh1);
            }
        }
        __syncthreads();
    }

    #pragma unroll
    for (int mt = 0; mt < 2; mt++) {
        int r0 = m0 + wm*32 + mt*16 + g;
        int r1 = r0 + 8;
        #pragma unroll
        for (int nt = 0; nt < 8; nt++) {
            int col = n0 + wn*64 + nt*8 + t4*2;
            float2 v0 = make_float2(acc[mt][nt][0], acc[mt][nt][1]);
            float2 v1 = make_float2(acc[mt][nt][2], acc[mt][nt][3]);
            if (Res) {
                float2 q0 = *(const float2*)(Res + (size_t)r0*N + col);
                float2 q1 = *(const float2*)(Res + (size_t)r1*N + col);
                v0.x += q0.x; v0.y += q0.y;
                v1.x += q1.x; v1.y += q1.y;
            }
            *(float2*)(C + (size_t)r0*N + col) = v0;
            *(float2*)(C + (size_t)r1*N + col) = v1;
        }
    }
}

// ============================================================
// RMSNorm -> fp16
// ============================================================
__global__ __launch_bounds__(256) void rmsnorm_kernel(
    const float* __restrict__ x, const float* __restrict__ w,
    __half* __restrict__ out_h)
{
    int row = blockIdx.x;
    int tid = threadIdx.x;
    const float4* xr = (const float4*)(x + (size_t)row*EMB);
    float4 v = xr[tid];
    float ss = v.x*v.x + v.y*v.y + v.z*v.z + v.w*v.w;
    #pragma unroll
    for (int o = 16; o > 0; o >>= 1) ss += __shfl_xor_sync(0xffffffffu, ss, o);
    __shared__ float wsum[8];
    if ((tid & 31) == 0) wsum[tid >> 5] = ss;
    __syncthreads();
    if (tid < 8) {
        float t = wsum[tid];
        #pragma unroll
        for (int o = 4; o > 0; o >>= 1) t += __shfl_xor_sync(0xffu, t, o);
        if (tid == 0) wsum[0] = t;
    }
    __syncthreads();
    float inv = rsqrtf(wsum[0] * (1.0f/EMB) + EPS);
    float4 wv = ((const float4*)w)[tid];
    __half2 h01 = __floats2half2_rn(v.x*inv*wv.x, v.y*inv*wv.y);
    __half2 h23 = __floats2half2_rn(v.z*inv*wv.z, v.w*inv*wv.w);
    uint2 hp;
    hp.x = *(uint32_t*)&h01; hp.y = *(uint32_t*)&h23;
    *(uint2*)(out_h + (size_t)row*EMB + tid*4) = hp;
}

// ============================================================
// prep_qk: RoPE + (q: scale 1/8) + fp16 -> [bh][s][64]
// ============================================================
__global__ __launch_bounds__(256) void prep_qk_kernel(
    const float* __restrict__ qkv, const float* __restrict__ cosb,
    const float* __restrict__ sinb,
    __half* __restrict__ qh, __half* __restrict__ kh)
{
    int idx = blockIdx.x * blockDim.x + threadIdx.x;   // 2^22
    int d  = idx & 31;
    int h  = (idx >> 5) & 15;
    int m  = (idx >> 9) & 4095;
    int t  = idx >> 21;                 // 0=q, 1=k
    int s  = m & (SEQ - 1);
    int b  = m >> 11;
    const float* p = qkv + (size_t)m*QKVN + t*EMB + h*HD;
    float x0 = p[d], x1 = p[d + 32];
    float c0 = cosb[s*HD + d],      c1 = cosb[s*HD + d + 32];
    float s0 = sinb[s*HD + d],      s1 = sinb[s*HD + d + 32];
    float r0 = c0*x0 + s0*x1;
    float r1 = c1*x1 + s1*x0;
    if (t == 0) { r0 *= 0.125f; r1 *= 0.125f; }
    __half* oh = (t ? kh : qh);
    size_t base = ((size_t)(b*NH + h)*SEQ + s)*HD;
    oh[base + d]      = __float2half_rn(r0);
    oh[base + d + 32] = __float2half_rn(r1);
}

// ============================================================
// prep_v: tiled transpose V -> [bh][d][s], fp16
// ============================================================
__global__ __launch_bounds__(256) void prep_v_kernel(
    const float* __restrict__ qkv, __half* __restrict__ vth)
{
    __shared__ float ts[64*65];
    int st = blockIdx.x * 64, h = blockIdx.y, b = blockIdx.z;
    int tid = threadIdx.x;
    int row = tid >> 2, seg = tid & 3;
    const float* src = qkv + (size_t)(b*SEQ + st + row)*QKVN + 2*EMB + h*HD;
    #pragma unroll
    for (int j = 0; j < 4; j++) {
        int f4 = seg*4 + j;
        float4 v = *(const float4*)(src + f4*4);
        ts[row*65 + f4*4+0] = v.x; ts[row*65 + f4*4+1] = v.y;
        ts[row*65 + f4*4+2] = v.z; ts[row*65 + f4*4+3] = v.w;
    }
    __syncthreads();
    int d = tid >> 2, ss = tid & 3;
    __half hv[16];
    #pragma unroll
    for (int j = 0; j < 16; j++)
        hv[j] = __float2half_rn(ts[(ss*16 + j)*65 + d]);
    size_t ob = ((size_t)((b*NH + h)*HD) + d)*SEQ + st + ss*16;
    #pragma unroll
    for (int j = 0; j < 4; j++) {
        __half2 a = __halves2half2(hv[4*j], hv[4*j+1]);
        __half2 c = __halves2half2(hv[4*j+2], hv[4*j+3]);
        uint2 pk; pk.x = *(uint32_t*)&a; pk.y = *(uint32_t*)&c;
        *(uint2*)(vth + ob + 4*j) = pk;
    }
}

// ============================================================
// Tensor-core causal flash attention (single-pass, 2 CTAs/SM)
// ============================================================
#define QROWS 128
#define KSTRW 36
#define QSZW  (QROWS*KSTRW)
#define KSZW  (64*KSTRW)
#define F_QH 0
#define F_KH QSZW                      // + buf*KSZW (2 bufs)
#define F_VH (QSZW + 2*KSZW)           // + buf*KSZW (2 bufs)
#define FLASH_SMEM ((QSZW + 4*KSZW)*4)   // 55296 bytes

__global__ __launch_bounds__(256, 2) void flash_mma_kernel(
    const __half* __restrict__ Qh, const __half* __restrict__ Kh,
    const __half* __restrict__ Vth, __half* __restrict__ attn_h)
{
    extern __shared__ __align__(16) uint32_t sf[];
    uint32_t sbase = smem_u32(sf);
    int tid = threadIdx.x, lane = tid & 31, wid = tid >> 5;
    int g = lane >> 2, t4 = lane & 3;
    int qt = (gridDim.x - 1) - blockIdx.x;
    int h = blockIdx.y, b = blockIdx.z;
    int bh = b*NH + h;
    int q0 = qt * QROWS;
    int nkt = 2*(qt + 1);

    const __half* gQh = Qh  + (size_t)bh*SEQ*HD;
    const __half* gKh = Kh  + (size_t)bh*SEQ*HD;
    const __half* gVh = Vth + (size_t)bh*HD*SEQ;

    auto issueKV = [&](int kt) {
        int k0 = kt * 64;
        uint32_t bufw = (uint32_t)(kt & 1) * KSZW;
        #pragma unroll
        for (int i = 0; i < 2; i++) {            // K hi: 512 tasks
            int task = tid + i*256;
            int row = task >> 3, seg = task & 7;
            const __half* src = gKh + (size_t)(k0 + row)*HD + seg*8;
            uint32_t dst = sbase + ((F_KH + bufw) + row*KSTRW + seg*4)*4;
            cp16(dst, src);
        }
        #pragma unroll
        for (int i = 0; i < 2; i++) {            // V hi: 512 tasks
            int task = tid + i*256;
            int row = task >> 3, seg = task & 7;
            const __half* src = gVh + (size_t)row*SEQ + k0 + seg*8;
            uint32_t dst = sbase + ((F_VH + bufw) + row*KSTRW + seg*4)*4;
            cp16(dst, src);
        }
    };

    #pragma unroll
    for (int i = 0; i < 4; i++) {                // Q hi: 1024 tasks
        int task = tid + i*256;
        int row = task >> 3, seg = task & 7;
        const __half* src = gQh + (size_t)(q0 + row)*HD + seg*8;
        uint32_t dst = sbase + (F_QH + row*KSTRW + seg*4)*4;
        cp16(dst, src);
    }
    issueKV(0);
    CP_COMMIT();

    float m0 = -INFINITY, m1 = -INFINITY, l0 = 0.f, l1 = 0.f;
    float o[8][4];
    #pragma unroll
    for (int dt = 0; dt < 8; dt++)
        #pragma unroll
        for (int e = 0; e < 4; e++) o[dt][e] = 0.f;

    const uint32_t* QhS = sf + F_QH;
    int qrow = (wid*16 + g) * KSTRW;

    for (int kt = 0; kt < nkt; kt++) {
        if (kt + 1 < nkt) { issueKV(kt + 1); CP_COMMIT(); CP_WAIT1(); }
        else              { CP_WAIT0(); }
        __syncthreads();

        uint32_t bufw = (uint32_t)(kt & 1) * KSZW;
        const uint32_t* KhS = sf + F_KH + bufw;
        const uint32_t* VhS = sf + F_VH + bufw;

        float sc[8][4];
        #pragma unroll
        for (int nt = 0; nt < 8; nt++)
            #pragma unroll
            for (int e = 0; e < 4; e++) sc[nt][e] = 0.f;

        #pragma unroll
        for (int s = 0; s < 4; s++) {
            int qo = qrow + s*8 + t4;
            uint32_t aH[4] = { QhS[qo], QhS[qo + 8*KSTRW], QhS[qo + 4], QhS[qo + 8*KSTRW + 4] };
            #pragma unroll
            for (int nt = 0; nt < 8; nt++) {
                int ko = (nt*8 + g)*KSTRW + s*8 + t4;
                mma_f16(sc[nt], aH, KhS[ko], KhS[ko + 4]);
            }
        }

        if (kt >= 2*qt) {
            int cb = kt*64;
            int r0 = q0 + wid*16 + g, r1 = r0 + 8;
            #pragma unroll
            for (int nt = 0; nt < 8; nt++) {
                int c0 = cb + nt*8 + 2*t4;
                if (c0     > r0) sc[nt][0] = -INFINITY;
                if (c0 + 1 > r0) sc[nt][1] = -INFINITY;
                if (c0     > r1) sc[nt][2] = -INFINITY;
                if (c0 + 1 > r1) sc[nt][3] = -INFINITY;
            }
        }

        float mt0 = -INFINITY, mt1 = -INFINITY;
        #pragma unroll
        for (int nt = 0; nt < 8; nt++) {
            mt0 = fmaxf(mt0, fmaxf(sc[nt][0], sc[nt][1]));
            mt1 = fmaxf(mt1, fmaxf(sc[nt][2], sc[nt][3]));
        }
        mt0 = fmaxf(mt0, __shfl_xor_sync(0xffffffffu, mt0, 1));
        mt0 = fmaxf(mt0, __shfl_xor_sync(0xffffffffu, mt0, 2));
        mt1 = fmaxf(mt1, __shfl_xor_sync(0xffffffffu, mt1, 1));
        mt1 = fmaxf(mt1, __shfl_xor_sync(0xffffffffu, mt1, 2));
        float mn0 = fmaxf(m0, mt0), mn1 = fmaxf(m1, mt1);
        float corr0 = __expf(m0 - mn0), corr1 = __expf(m1 - mn1);
        m0 = mn0; m1 = mn1;

        float ls0 = 0.f, ls1 = 0.f;
        uint32_t phA[8], phB[8];
        #pragma unroll
        for (int nt = 0; nt < 8; nt++) {
            float p0 = __expf(sc[nt][0] - mn0);
            float p1 = __expf(sc[nt][1] - mn0);
            float p2 = __expf(sc[nt][2] - mn1);
            float p3 = __expf(sc[nt][3] - mn1);
            ls0 += p0 + p1;  ls1 += p2 + p3;
            __half2 hA = __floats2half2_rn(p0, p1);
            __half2 hB = __floats2half2_rn(p2, p3);
            phA[nt] = *(uint32_t*)&hA;
            phB[nt] = *(uint32_t*)&hB;
        }
        ls0 += __shfl_xor_sync(0xffffffffu, ls0, 1);
        ls0 += __shfl_xor_sync(0xffffffffu, ls0, 2);
        ls1 += __shfl_xor_sync(0xffffffffu, ls1, 1);
        ls1 += __shfl_xor_sync(0xffffffffu, ls1, 2);
        l0 = l0*corr0 + ls0;
        l1 = l1*corr1 + ls1;
        #pragma unroll
        for (int dt = 0; dt < 8; dt++) {
            o[dt][0] *= corr0; o[dt][1] *= corr0;
            o[dt][2] *= corr1; o[dt][3] *= corr1;
        }

        #pragma unroll
        for (int kk = 0; kk < 4; kk++) {
            uint32_t aH[4] = { phA[2*kk], phB[2*kk], phA[2*kk+1], phB[2*kk+1] };
            #pragma unroll
            for (int dt = 0; dt < 8; dt++) {
                int vo = (dt*8 + g)*KSTRW + kk*8 + t4;
                mma_f16(o[dt], aH, VhS[vo], VhS[vo + 4]);
            }
        }
        __syncthreads();
    }

    float il0 = 1.0f / l0, il1 = 1.0f / l1;
    int r0g = b*SEQ + q0 + wid*16 + g;
    int r1g = r0g + 8;
    int cbase = h*HD;
    #pragma unroll
    for (int dt = 0; dt < 8; dt++) {
        int c = cbase + dt*8 + 2*t4;
        __half2 ha = __floats2half2_rn(o[dt][0]*il0, o[dt][1]*il0);
        __half2 hb = __floats2half2_rn(o[dt][2]*il1, o[dt][3]*il1);
        *(uint32_t*)(attn_h + (size_t)r0g*EMB + c) = *(uint32_t*)&ha;
        *(uint32_t*)(attn_h + (size_t)r1g*EMB + c) = *(uint32_t*)&hb;
    }
}

// ============================================================
// launch
// ============================================================
extern "C" void kernel_launch(void* const* d_in, const int* in_sizes, int n_in,
                              void* d_out, int out_size)
{
    const float* emb  = (const float*)d_in[0];
    const float* cosb = (const float*)d_in[1];
    const float* sinb = (const float*)d_in[2];
    const float* nw   = (const float*)d_in[3];
    const float* qkvw = (const float*)d_in[4];
    const float* ow   = (const float*)d_in[5];
    float* out = (float*)d_out;

    float* qkv;
    __half *nh, *ah, *wqh, *woh, *qh, *kh, *vth;
    cudaGetSymbolAddress((void**)&qkv, g_qkv);
    cudaGetSymbolAddress((void**)&nh,  g_nrm_h);
    cudaGetSymbolAddress((void**)&ah,  g_att_h);
    cudaGetSymbolAddress((void**)&wqh, g_wqkv_h);
    cudaGetSymbolAddress((void**)&woh, g_wo_h);
    cudaGetSymbolAddress((void**)&qh,  g_qh);
    cudaGetSymbolAddress((void**)&kh,  g_kh);
    cudaGetSymbolAddress((void**)&vth, g_vth);

    cudaFuncSetAttribute(gemm_f16_kernel,
        cudaFuncAttributeMaxDynamicSharedMemorySize, GEMM_SMEM);
    cudaFuncSetAttribute(flash_mma_kernel,
        cudaFuncAttributeMaxDynamicSharedMemorySize, FLASH_SMEM);

    conv_hi_kernel<<<(QKVN*EMB/4)/256, 256>>>(qkvw, wqh);
    conv_hi_kernel<<<(EMB*EMB/4)/256, 256>>>(ow, woh);
    rmsnorm_kernel<<<MROWS, 256>>>(emb, nw, nh);
    gemm_f16_kernel<<<dim3(QKVN/128, MROWS/128), 256, GEMM_SMEM>>>(
        nh, wqh, nullptr, qkv, QKVN);
    prep_qk_kernel<<<(2*MROWS*NH*32)/256, 256>>>(qkv, cosb, sinb, qh, kh);
    prep_v_kernel<<<dim3(SEQ/64, NH, BATCH), 256>>>(qkv, vth);
    flash_mma_kernel<<<dim3(SEQ/QROWS, NH, BATCH), 256, FLASH_SMEM>>>(
        qh, kh, vth, ah);
    gemm_f16_kernel<<<dim3(EMB/128, MROWS/128), 256, GEMM_SMEM>>>(
        ah, woh, emb, out, EMB);
}

// round 16
// speedup vs baseline: 3.2562x; 1.0485x over previous
#include <cuda_runtime.h>
#include <cuda_fp16.h>
#include <math.h>
#include <stdint.h>

#define EMB   1024
#define NH    16
#define HD    64
#define SEQ   2048
#define BATCH 2
#define MROWS (BATCH*SEQ)     // 4096
#define QKVN  (3*EMB)         // 3072
#define EPS   1.1920929e-07f

// ---- scratch (no allocations allowed) ----
__device__ __half g_nrm_h[(size_t)MROWS*EMB];
__device__ __half g_att_h[(size_t)MROWS*EMB];
__device__ __half g_wqkv_h[(size_t)QKVN*EMB];
__device__ __half g_wo_h[(size_t)EMB*EMB];
__device__ __half g_qh[(size_t)BATCH*NH*SEQ*HD];
__device__ __half g_kh[(size_t)BATCH*NH*SEQ*HD];
__device__ __half g_v[(size_t)MROWS*EMB];
__device__ __half g_vth[(size_t)BATCH*NH*HD*SEQ];

// ============================================================
// helpers
// ============================================================
__device__ __forceinline__ uint32_t smem_u32(const void* p) {
    uint32_t a;
    asm("{ .reg .u64 t; cvta.to.shared.u64 t, %1; cvt.u32.u64 %0, t; }" : "=r"(a) : "l"(p));
    return a;
}
__device__ __forceinline__ void mma_f16(float* c, const uint32_t* a,
                                        uint32_t b0, uint32_t b1) {
    asm volatile(
        "mma.sync.aligned.m16n8k16.row.col.f32.f16.f16.f32 "
        "{%0,%1,%2,%3}, {%4,%5,%6,%7}, {%8,%9}, {%0,%1,%2,%3};"
        : "+f"(c[0]), "+f"(c[1]), "+f"(c[2]), "+f"(c[3])
        : "r"(a[0]), "r"(a[1]), "r"(a[2]), "r"(a[3]), "r"(b0), "r"(b1));
}
__device__ __forceinline__ void cp16(uint32_t sdst, const void* gsrc) {
    asm volatile("cp.async.cg.shared.global [%0], [%1], 16;" :: "r"(sdst), "l"(gsrc));
}
#define CP_COMMIT() asm volatile("cp.async.commit_group;")
#define CP_WAIT1()  asm volatile("cp.async.wait_group 1;")
#define CP_WAIT0()  asm volatile("cp.async.wait_group 0;")

// ============================================================
// weight fp16 conversion
// ============================================================
__global__ __launch_bounds__(256) void conv_hi_kernel(
    const float* __restrict__ x, __half* __restrict__ hi)
{
    int i = blockIdx.x * 256 + threadIdx.x;
    float4 v = ((const float4*)x)[i];
    __half2 h01 = __floats2half2_rn(v.x, v.y);
    __half2 h23 = __floats2half2_rn(v.z, v.w);
    uint2 hp;
    hp.x = *(uint32_t*)&h01; hp.y = *(uint32_t*)&h23;
    *(uint2*)(hi + (size_t)i*4) = hp;
}

// ============================================================
// shared GEMM mainloop config
// CTA tile 128(M) x 128(N), K-chunk 64, double-buffered, 2 CTAs/SM
// ============================================================
#define STRW  36                      // words (u32) per smem row (72 halfs)
#define TWA   (128*STRW)
#define BUFW  (2*TWA)
#define OFF_AH 0
#define OFF_BH TWA
#define GEMM_SMEM (2*BUFW*4)          // 147456 bytes

#define GEMM_MAINLOOP(ACC) \
    auto issue = [&](int ch) { \
        int k0 = ch * 64; \
        uint32_t bufw = (uint32_t)(ch & 1) * BUFW; \
        _Pragma("unroll") \
        for (int i = 0; i < 8; i++) { \
            int task = tid + i * 256; \
            int piece = task >> 10; \
            int rem = task & 1023; \
            int row = rem >> 3, seg = rem & 7; \
            const __half* src = (piece ? Bh : Ah) + (size_t)((piece ? n0 : m0) + row)*1024 + k0 + seg*8; \
            uint32_t sa = sbase + (bufw + (piece ? OFF_BH : OFF_AH) + row*STRW + seg*4)*4; \
            cp16(sa, src); \
        } \
        CP_COMMIT(); \
    }; \
    issue(0); \
    for (int ch = 0; ch < 16; ch++) { \
        if (ch + 1 < 16) { issue(ch + 1); CP_WAIT1(); } \
        else             { CP_WAIT0(); } \
        __syncthreads(); \
        uint32_t bufw = (uint32_t)(ch & 1) * BUFW; \
        const uint32_t* AsH = sg + bufw + OFF_AH; \
        const uint32_t* BsH = sg + bufw + OFF_BH; \
        _Pragma("unroll") \
        for (int s = 0; s < 4; s++) { \
            uint32_t aH[2][4]; \
            _Pragma("unroll") \
            for (int mt = 0; mt < 2; mt++) { \
                int o = (wm*32 + mt*16 + g)*STRW + s*8 + t4; \
                aH[mt][0] = AsH[o];           aH[mt][1] = AsH[o + 8*STRW]; \
                aH[mt][2] = AsH[o + 4];       aH[mt][3] = AsH[o + 8*STRW + 4]; \
            } \
            _Pragma("unroll") \
            for (int nt = 0; nt < 8; nt++) { \
                int o = (wn*64 + nt*8 + g)*STRW + s*8 + t4; \
                uint32_t bh0 = BsH[o], bh1 = BsH[o + 4]; \
                _Pragma("unroll") \
                for (int mt = 0; mt < 2; mt++) \
                    mma_f16(ACC[mt][nt], aH[mt], bh0, bh1); \
            } \
        } \
        __syncthreads(); \
    }

// ============================================================
// QKV GEMM with fused RoPE/scale/layout epilogue
// ============================================================
__global__ __launch_bounds__(256, 2) void gemm_qkv_kernel(
    const __half* __restrict__ Ah, const __half* __restrict__ Bh,
    const float* __restrict__ cosb, const float* __restrict__ sinb,
    __half* __restrict__ qh, __half* __restrict__ kh, __half* __restrict__ vv)
{
    extern __shared__ __align__(16) uint32_t sg[];
    uint32_t sbase = smem_u32(sg);
    int tid = threadIdx.x;
    int m0 = blockIdx.y * 128, n0 = blockIdx.x * 128;
    int lane = tid & 31, wid = tid >> 5;
    int g = lane >> 2, t4 = lane & 3;
    int wm = wid & 3, wn = wid >> 2;

    float acc[2][8][4];
    #pragma unroll
    for (int mt = 0; mt < 2; mt++)
        #pragma unroll
        for (int nt = 0; nt < 8; nt++)
            #pragma unroll
            for (int r = 0; r < 4; r++) acc[mt][nt][r] = 0.0f;

    GEMM_MAINLOOP(acc)

    int region = n0 >> 10;                    // 0=q, 1=k, 2=v
    int colbase = (n0 & 1023) + wn*64;        // offset within region
    if (region < 2) {
        int h = colbase >> 6;
        __half* dst = region ? kh : qh;
        float scale = region ? 1.0f : 0.125f;
        #pragma unroll
        for (int mt = 0; mt < 2; mt++) {
            #pragma unroll
            for (int rr = 0; rr < 2; rr++) {
                int m = m0 + wm*32 + mt*16 + g + rr*8;
                int s = m & (SEQ - 1), b = m >> 11;
                size_t base = ((size_t)(b*NH + h)*SEQ + s)*HD;
                const float* cb = cosb + s*HD;
                const float* sb = sinb + s*HD;
                #pragma unroll
                for (int nt = 0; nt < 4; nt++) {
                    int d = nt*8 + t4*2;
                    float x0 = acc[mt][nt][rr*2+0],   x1 = acc[mt][nt][rr*2+1];
                    float y0 = acc[mt][nt+4][rr*2+0], y1 = acc[mt][nt+4][rr*2+1];
                    float2 cd = *(const float2*)(cb + d);
                    float2 sd = *(const float2*)(sb + d);
                    float2 ce = *(const float2*)(cb + d + 32);
                    float2 se = *(const float2*)(sb + d + 32);
                    float r0v = (cd.x*x0 + sd.x*y0)*scale;
                    float r1v = (cd.y*x1 + sd.y*y1)*scale;
                    float e0v = (ce.x*y0 + se.x*x0)*scale;
                    float e1v = (ce.y*y1 + se.y*x1)*scale;
                    __half2 hd = __floats2half2_rn(r0v, r1v);
                    __half2 he = __floats2half2_rn(e0v, e1v);
                    *(uint32_t*)(dst + base + d)      = *(uint32_t*)&hd;
                    *(uint32_t*)(dst + base + d + 32) = *(uint32_t*)&he;
                }
            }
        }
    } else {
        #pragma unroll
        for (int mt = 0; mt < 2; mt++) {
            int r0 = m0 + wm*32 + mt*16 + g;
            #pragma unroll
            for (int nt = 0; nt < 8; nt++) {
                int o = colbase + nt*8 + t4*2;
                __half2 h0 = __floats2half2_rn(acc[mt][nt][0], acc[mt][nt][1]);
                __half2 h1 = __floats2half2_rn(acc[mt][nt][2], acc[mt][nt][3]);
                *(uint32_t*)(vv + (size_t)r0*EMB + o)     = *(uint32_t*)&h0;
                *(uint32_t*)(vv + (size_t)(r0+8)*EMB + o) = *(uint32_t*)&h1;
            }
        }
    }
}

// ============================================================
// out-proj GEMM (+ residual)
// ============================================================
__global__ __launch_bounds__(256, 2) void gemm_f16_kernel(
    const __half* __restrict__ Ah, const __half* __restrict__ Bh,
    const float* __restrict__ Res, float* __restrict__ C, int N)
{
    extern __shared__ __align__(16) uint32_t sg[];
    uint32_t sbase = smem_u32(sg);
    int tid = threadIdx.x;
    int m0 = blockIdx.y * 128, n0 = blockIdx.x * 128;
    int lane = tid & 31, wid = tid >> 5;
    int g = lane >> 2, t4 = lane & 3;
    int wm = wid & 3, wn = wid >> 2;

    float acc[2][8][4];
    #pragma unroll
    for (int mt = 0; mt < 2; mt++)
        #pragma unroll
        for (int nt = 0; nt < 8; nt++)
            #pragma unroll
            for (int r = 0; r < 4; r++) acc[mt][nt][r] = 0.0f;

    GEMM_MAINLOOP(acc)

    #pragma unroll
    for (int mt = 0; mt < 2; mt++) {
        int r0 = m0 + wm*32 + mt*16 + g;
        int r1 = r0 + 8;
        #pragma unroll
        for (int nt = 0; nt < 8; nt++) {
            int col = n0 + wn*64 + nt*8 + t4*2;
            float2 v0 = make_float2(acc[mt][nt][0], acc[mt][nt][1]);
            float2 v1 = make_float2(acc[mt][nt][2], acc[mt][nt][3]);
            float2 q0 = *(const float2*)(Res + (size_t)r0*N + col);
            float2 q1 = *(const float2*)(Res + (size_t)r1*N + col);
            v0.x += q0.x; v0.y += q0.y;
            v1.x += q1.x; v1.y += q1.y;
            *(float2*)(C + (size_t)r0*N + col) = v0;
            *(float2*)(C + (size_t)r1*N + col) = v1;
        }
    }
}

// ============================================================
// RMSNorm -> fp16
// ============================================================
__global__ __launch_bounds__(256) void rmsnorm_kernel(
    const float* __restrict__ x, const float* __restrict__ w,
    __half* __restrict__ out_h)
{
    int row = blockIdx.x;
    int tid = threadIdx.x;
    const float4* xr = (const float4*)(x + (size_t)row*EMB);
    float4 v = xr[tid];
    float ss = v.x*v.x + v.y*v.y + v.z*v.z + v.w*v.w;
    #pragma unroll
    for (int o = 16; o > 0; o >>= 1) ss += __shfl_xor_sync(0xffffffffu, ss, o);
    __shared__ float wsum[8];
    if ((tid & 31) == 0) wsum[tid >> 5] = ss;
    __syncthreads();
    if (tid < 8) {
        float t = wsum[tid];
        #pragma unroll
        for (int o = 4; o > 0; o >>= 1) t += __shfl_xor_sync(0xffu, t, o);
        if (tid == 0) wsum[0] = t;
    }
    __syncthreads();
    float inv = rsqrtf(wsum[0] * (1.0f/EMB) + EPS);
    float4 wv = ((const float4*)w)[tid];
    __half2 h01 = __floats2half2_rn(v.x*inv*wv.x, v.y*inv*wv.y);
    __half2 h23 = __floats2half2_rn(v.z*inv*wv.z, v.w*inv*wv.w);
    uint2 hp;
    hp.x = *(uint32_t*)&h01; hp.y = *(uint32_t*)&h23;
    *(uint2*)(out_h + (size_t)row*EMB + tid*4) = hp;
}

// ============================================================
// prep_v: fp16 transpose V -> [bh][d][s]
// ============================================================
__global__ __launch_bounds__(256) void prep_v_kernel(
    const __half* __restrict__ vv, __half* __restrict__ vth)
{
    __shared__ __half ts[64*72];
    int st = blockIdx.x * 64, h = blockIdx.y, b = blockIdx.z;
    int tid = threadIdx.x;
    int row = tid >> 2, seg = tid & 3;
    const __half* src = vv + (size_t)(b*SEQ + st + row)*EMB + h*HD + seg*16;
    uint4 u0 = *(const uint4*)(src);
    uint4 u1 = *(const uint4*)(src + 8);
    *(uint4*)&ts[row*72 + seg*16]     = u0;
    *(uint4*)&ts[row*72 + seg*16 + 8] = u1;
    __syncthreads();
    int d = tid >> 2, ss = tid & 3;
    __half hv[16];
    #pragma unroll
    for (int j = 0; j < 16; j++)
        hv[j] = ts[(ss*16 + j)*72 + d];
    size_t ob = ((size_t)((b*NH + h)*HD) + d)*SEQ + st + ss*16;
    *(uint4*)(vth + ob)     = *(uint4*)&hv[0];
    *(uint4*)(vth + ob + 8) = *(uint4*)&hv[8];
}

// ============================================================
// Tensor-core causal flash attention (single-pass, 2 CTAs/SM)
// ============================================================
#define QROWS 128
#define KSTRW 36
#define QSZW  (QROWS*KSTRW)
#define KSZW  (64*KSTRW)
#define F_QH 0
#define F_KH QSZW
#define F_VH (QSZW + 2*KSZW)
#define FLASH_SMEM ((QSZW + 4*KSZW)*4)   // 55296 bytes

__global__ __launch_bounds__(256, 2) void flash_mma_kernel(
    const __half* __restrict__ Qh, const __half* __restrict__ Kh,
    const __half* __restrict__ Vth, __half* __restrict__ attn_h)
{
    extern __shared__ __align__(16) uint32_t sf[];
    uint32_t sbase = smem_u32(sf);
    int tid = threadIdx.x, lane = tid & 31, wid = tid >> 5;
    int g = lane >> 2, t4 = lane & 3;
    int qt = (gridDim.x - 1) - blockIdx.x;
    int h = blockIdx.y, b = blockIdx.z;
    int bh = b*NH + h;
    int q0 = qt * QROWS;
    int nkt = 2*(qt + 1);

    const __half* gQh = Qh  + (size_t)bh*SEQ*HD;
    const __half* gKh = Kh  + (size_t)bh*SEQ*HD;
    const __half* gVh = Vth + (size_t)bh*HD*SEQ;

    auto issueKV = [&](int kt) {
        int k0 = kt * 64;
        uint32_t bufw = (uint32_t)(kt & 1) * KSZW;
        #pragma unroll
        for (int i = 0; i < 2; i++) {
            int task = tid + i*256;
            int row = task >> 3, seg = task & 7;
            const __half* src = gKh + (size_t)(k0 + row)*HD + seg*8;
            uint32_t dst = sbase + ((F_KH + bufw) + row*KSTRW + seg*4)*4;
            cp16(dst, src);
        }
        #pragma unroll
        for (int i = 0; i < 2; i++) {
            int task = tid + i*256;
            int row = task >> 3, seg = task & 7;
            const __half* src = gVh + (size_t)row*SEQ + k0 + seg*8;
            uint32_t dst = sbase + ((F_VH + bufw) + row*KSTRW + seg*4)*4;
            cp16(dst, src);
        }
    };

    #pragma unroll
    for (int i = 0; i < 4; i++) {
        int task = tid + i*256;
        int row = task >> 3, seg = task & 7;
        const __half* src = gQh + (size_t)(q0 + row)*HD + seg*8;
        uint32_t dst = sbase + (F_QH + row*KSTRW + seg*4)*4;
        cp16(dst, src);
    }
    issueKV(0);
    CP_COMMIT();

    float m0 = -INFINITY, m1 = -INFINITY, l0 = 0.f, l1 = 0.f;
    float o[8][4];
    #pragma unroll
    for (int dt = 0; dt < 8; dt++)
        #pragma unroll
        for (int e = 0; e < 4; e++) o[dt][e] = 0.f;

    const uint32_t* QhS = sf + F_QH;
    int qrow = (wid*16 + g) * KSTRW;

    for (int kt = 0; kt < nkt; kt++) {
        if (kt + 1 < nkt) { issueKV(kt + 1); CP_COMMIT(); CP_WAIT1(); }
        else              { CP_WAIT0(); }
        __syncthreads();

        uint32_t bufw = (uint32_t)(kt & 1) * KSZW;
        const uint32_t* KhS = sf + F_KH + bufw;
        const uint32_t* VhS = sf + F_VH + bufw;

        float sc[8][4];
        #pragma unroll
        for (int nt = 0; nt < 8; nt++)
            #pragma unroll
            for (int e = 0; e < 4; e++) sc[nt][e] = 0.f;

        #pragma unroll
        for (int s = 0; s < 4; s++) {
            int qo = qrow + s*8 + t4;
            uint32_t aH[4] = { QhS[qo], QhS[qo + 8*KSTRW], QhS[qo + 4], QhS[qo + 8*KSTRW + 4] };
            #pragma unroll
            for (int nt = 0; nt < 8; nt++) {
                int ko = (nt*8 + g)*KSTRW + s*8 + t4;
                mma_f16(sc[nt], aH, KhS[ko], KhS[ko + 4]);
            }
        }

        if (kt >= 2*qt) {
            int cb = kt*64;
            int r0 = q0 + wid*16 + g, r1 = r0 + 8;
            #pragma unroll
            for (int nt = 0; nt < 8; nt++) {
                int c0 = cb + nt*8 + 2*t4;
                if (c0     > r0) sc[nt][0] = -INFINITY;
                if (c0 + 1 > r0) sc[nt][1] = -INFINITY;
                if (c0     > r1) sc[nt][2] = -INFINITY;
                if (c0 + 1 > r1) sc[nt][3] = -INFINITY;
            }
        }

        float mt0 = -INFINITY, mt1 = -INFINITY;
        #pragma unroll
        for (int nt = 0; nt < 8; nt++) {
            mt0 = fmaxf(mt0, fmaxf(sc[nt][0], sc[nt][1]));
            mt1 = fmaxf(mt1, fmaxf(sc[nt][2], sc[nt][3]));
        }
        mt0 = fmaxf(mt0, __shfl_xor_sync(0xffffffffu, mt0, 1));
        mt0 = fmaxf(mt0, __shfl_xor_sync(0xffffffffu, mt0, 2));
        mt1 = fmaxf(mt1, __shfl_xor_sync(0xffffffffu, mt1, 1));
        mt1 = fmaxf(mt1, __shfl_xor_sync(0xffffffffu, mt1, 2));
        float mn0 = fmaxf(m0, mt0), mn1 = fmaxf(m1, mt1);
        float corr0 = __expf(m0 - mn0), corr1 = __expf(m1 - mn1);
        m0 = mn0; m1 = mn1;

        float ls0 = 0.f, ls1 = 0.f;
        uint32_t phA[8], phB[8];
        #pragma unroll
        for (int nt = 0; nt < 8; nt++) {
            float p0 = __expf(sc[nt][0] - mn0);
            float p1 = __expf(sc[nt][1] - mn0);
            float p2 = __expf(sc[nt][2] - mn1);
            float p3 = __expf(sc[nt][3] - mn1);
            ls0 += p0 + p1;  ls1 += p2 + p3;
            __half2 hA = __floats2half2_rn(p0, p1);
            __half2 hB = __floats2half2_rn(p2, p3);
            phA[nt] = *(uint32_t*)&hA;
            phB[nt] = *(uint32_t*)&hB;
        }
        ls0 += __shfl_xor_sync(0xffffffffu, ls0, 1);
        ls0 += __shfl_xor_sync(0xffffffffu, ls0, 2);
        ls1 += __shfl_xor_sync(0xffffffffu, ls1, 1);
        ls1 += __shfl_xor_sync(0xffffffffu, ls1, 2);
        l0 = l0*corr0 + ls0;
        l1 = l1*corr1 + ls1;
        #pragma unroll
        for (int dt = 0; dt < 8; dt++) {
            o[dt][0] *= corr0; o[dt][1] *= corr0;
            o[dt][2] *= corr1; o[dt][3] *= corr1;
        }

        #pragma unroll
        for (int kk = 0; kk < 4; kk++) {
            uint32_t aH[4] = { phA[2*kk], phB[2*kk], phA[2*kk+1], phB[2*kk+1] };
            #pragma unroll
            for (int dt = 0; dt < 8; dt++) {
                int vo = (dt*8 + g)*KSTRW + kk*8 + t4;
                mma_f16(o[dt], aH, VhS[vo], VhS[vo + 4]);
            }
        }
        __syncthreads();
    }

    float il0 = 1.0f / l0, il1 = 1.0f / l1;
    int r0g = b*SEQ + q0 + wid*16 + g;
    int r1g = r0g + 8;
    int cbase = h*HD;
    #pragma unroll
    for (int dt = 0; dt < 8; dt++) {
        int c = cbase + dt*8 + 2*t4;
        __half2 ha = __floats2half2_rn(o[dt][0]*il0, o[dt][1]*il0);
        __half2 hb = __floats2half2_rn(o[dt][2]*il1, o[dt][3]*il1);
        *(uint32_t*)(attn_h + (size_t)r0g*EMB + c) = *(uint32_t*)&ha;
        *(uint32_t*)(attn_h + (size_t)r1g*EMB + c) = *(uint32_t*)&hb;
    }
}

// ============================================================
// launch
// ============================================================
extern "C" void kernel_launch(void* const* d_in, const int* in_sizes, int n_in,
                              void* d_out, int out_size)
{
    const float* emb  = (const float*)d_in[0];
    const float* cosb = (const float*)d_in[1];
    const float* sinb = (const float*)d_in[2];
    const float* nw   = (const float*)d_in[3];
    const float* qkvw = (const float*)d_in[4];
    const float* ow   = (const float*)d_in[5];
    float* out = (float*)d_out;

    __half *nh, *ah, *wqh, *woh, *qh, *kh, *vv, *vth;
    cudaGetSymbolAddress((void**)&nh,  g_nrm_h);
    cudaGetSymbolAddress((void**)&ah,  g_att_h);
    cudaGetSymbolAddress((void**)&wqh, g_wqkv_h);
    cudaGetSymbolAddress((void**)&woh, g_wo_h);
    cudaGetSymbolAddress((void**)&qh,  g_qh);
    cudaGetSymbolAddress((void**)&kh,  g_kh);
    cudaGetSymbolAddress((void**)&vv,  g_v);
    cudaGetSymbolAddress((void**)&vth, g_vth);

    cudaFuncSetAttribute(gemm_qkv_kernel,
        cudaFuncAttributeMaxDynamicSharedMemorySize, GEMM_SMEM);
    cudaFuncSetAttribute(gemm_f16_kernel,
        cudaFuncAttributeMaxDynamicSharedMemorySize, GEMM_SMEM);
    cudaFuncSetAttribute(flash_mma_kernel,
        cudaFuncAttributeMaxDynamicSharedMemorySize, FLASH_SMEM);

    conv_hi_kernel<<<(QKVN*EMB/4)/256, 256>>>(qkvw, wqh);
    conv_hi_kernel<<<(EMB*EMB/4)/256, 256>>>(ow, woh);
    rmsnorm_kernel<<<MROWS, 256>>>(emb, nw, nh);
    gemm_qkv_kernel<<<dim3(QKVN/128, MROWS/128), 256, GEMM_SMEM>>>(
        nh, wqh, cosb, sinb, qh, kh, vv);
    prep_v_kernel<<<dim3(SEQ/64, NH, BATCH), 256>>>(vv, vth);
    flash_mma_kernel<<<dim3(SEQ/QROWS, NH, BATCH), 256, FLASH_SMEM>>>(
        qh, kh, vth, ah);
    gemm_f16_kernel<<<dim3(EMB/128, MROWS/128), 256, GEMM_SMEM>>>(
        ah, woh, emb, out, EMB);
}